// round 3
// baseline (speedup 1.0000x reference)
#include <cuda_runtime.h>
#include <math.h>

#define CB     96
#define HWIMG  128
#define HW     16384          // 128*128
#define NB     2
#define NELEM  3145728        // NB*CB*HW
#define NWIN   31
#define NWINDOWS 1922         // NB*31*31
#define ATT_SCALE 0.20412414523193154f  // 1/sqrt(24)

// ---------------- scratch (static device globals; alloc-free rule) -------------
__device__ float g_l1[NELEM], g_h1[NELEM];
__device__ float g_QL[NELEM], g_KL[NELEM], g_VL[NELEM];
__device__ float g_QH[NELEM], g_KH[NELEM], g_VH[NELEM];
__device__ float g_accL[NELEM], g_accH[NELEM];
__device__ float g_low1[NELEM], g_high1[NELEM];
__device__ float g_low2[NELEM], g_high2[NELEM];
__device__ float g_pool[NB*CB], g_se[NB*CB];

// ---------------- helpers ------------------------------------------------------
__device__ __forceinline__ float cnt1f(int h) {
    // number of stride-4 size-8 windows (indices 0..30) covering coordinate h
    int imin = (h <= 7) ? 0 : ((h - 4) >> 2);
    int imax = min(30, h >> 2);
    return (float)(imax - imin + 1);
}

// ---------------- LN over channel axis, per pixel ------------------------------
// grid (NB*H, 2), 256 thr, dyn smem 50176B
__global__ void k_ln(const float* __restrict__ srcL, const float* __restrict__ srcH,
                     const float* __restrict__ gw,  const float* __restrict__ bw,
                     float* __restrict__ dstL, float* __restrict__ dstH)
{
    extern __shared__ float sm[];
    float* Xs = sm;              // 96*128
    float* mu = sm + 12288;      // 128
    float* rv = sm + 12416;      // 128
    const float* src = blockIdx.y ? srcH : srcL;
    float*       dst = blockIdx.y ? dstH : dstL;
    int row = blockIdx.x;
    int b = row >> 7, h = row & 127;
    int base = b * CB * HW + h * 128;
    int tid = threadIdx.x;

    for (int i = tid; i < 12288; i += 256) {
        int c = i >> 7, p = i & 127;
        Xs[i] = src[base + c * HW + p];
    }
    __syncthreads();
    if (tid < 128) {
        float s = 0.f, s2 = 0.f;
        #pragma unroll 8
        for (int c = 0; c < CB; c++) {
            float v = Xs[c * 128 + tid];
            s += v; s2 += v * v;
        }
        float m = s * (1.f / 96.f);
        float var = s2 * (1.f / 96.f) - m * m;
        mu[tid] = m;
        rv[tid] = rsqrtf(var + 1e-5f);
    }
    __syncthreads();
    for (int i = tid; i < 12288; i += 256) {
        int c = i >> 7, p = i & 127;
        dst[base + c * HW + p] = (Xs[i] - mu[p]) * rv[p] * gw[c] + bw[c];
    }
}

// ---------------- SE: spatial mean pool per (b,c) ------------------------------
// grid NB*CB, 256 thr
__global__ void k_pool(const float* __restrict__ h1, float* __restrict__ pool)
{
    int bc = blockIdx.x;
    const float* p = h1 + bc * HW;
    float s = 0.f;
    for (int i = threadIdx.x; i < HW; i += 256) s += p[i];
    __shared__ float red[256];
    red[threadIdx.x] = s; __syncthreads();
    for (int o = 128; o > 0; o >>= 1) {
        if (threadIdx.x < o) red[threadIdx.x] += red[threadIdx.x + o];
        __syncthreads();
    }
    if (threadIdx.x == 0) pool[bc] = red[0] * (1.f / 16384.f);
}

// ---------------- SE: FC -> relu -> FC -> sigmoid (tiny) -----------------------
__global__ void k_se(const float* __restrict__ pool, const float* __restrict__ w1,
                     const float* __restrict__ w2, float* __restrict__ se)
{
    int t = threadIdx.x;
    if (t >= NB * CB) return;
    int b = t / CB, c = t % CB;
    int gi = c >> 5, j = c & 31;
    const float* pl = pool + b * CB + gi * 32;
    float z0 = 0.f, z1 = 0.f;
    #pragma unroll
    for (int g = 0; g < 32; g++) {
        float pv = pl[g];
        z0 += pv * w1[gi * 64 + g];
        z1 += pv * w1[gi * 64 + 32 + g];
    }
    z0 = fmaxf(z0, 0.f); z1 = fmaxf(z1, 0.f);
    float a = z0 * w2[gi * 64 + j * 2] + z1 * w2[gi * 64 + j * 2 + 1];
    se[t] = 1.f / (1.f + __expf(-a));
}

// ---------------- 6 per-pixel projections (96x96 GEMMs over image) -------------
// grid (NB*H, 6), 256 thr, dyn smem 86016B
__global__ __launch_bounds__(256, 2)
void k_proj6(const float* __restrict__ l1, const float* __restrict__ h1,
             const float* __restrict__ se,
             const float* __restrict__ Wql, const float* __restrict__ Wkl, const float* __restrict__ Wvl,
             const float* __restrict__ Wqh, const float* __restrict__ Wkh, const float* __restrict__ Wvh,
             float* __restrict__ QL, float* __restrict__ KL, float* __restrict__ VL,
             float* __restrict__ QH, float* __restrict__ KH, float* __restrict__ VH)
{
    extern __shared__ float sm[];
    float* Ws = sm;           // 9216
    float* Xs = sm + 9216;    // 12288
    int row = blockIdx.x;
    int j = blockIdx.y;
    const float* W; const float* X; float* O; bool useSE;
    switch (j) {
        case 0: W = Wql; X = l1; O = QL; useSE = false; break;
        case 1: W = Wkl; X = l1; O = KL; useSE = false; break;
        case 2: W = Wvl; X = l1; O = VL; useSE = false; break;
        case 3: W = Wqh; X = h1; O = QH; useSE = true;  break;
        case 4: W = Wkh; X = h1; O = KH; useSE = true;  break;
        default: W = Wvh; X = h1; O = VH; useSE = true; break;
    }
    int b = row >> 7, h = row & 127;
    int base = b * CB * HW + h * 128;
    int tid = threadIdx.x;

    for (int i = tid; i < 9216; i += 256) Ws[i] = W[i];
    for (int i = tid; i < 12288; i += 256) {
        int c = i >> 7, p = i & 127;
        float v = X[base + c * HW + p];
        if (useSE) v *= se[b * CB + c];
        Xs[i] = v;
    }
    __syncthreads();

    int og = tid >> 4, pg = tid & 15;   // rows og*6..+5, cols pg*8..+7
    float acc[6][8];
    #pragma unroll
    for (int r = 0; r < 6; r++)
        #pragma unroll
        for (int i = 0; i < 8; i++) acc[r][i] = 0.f;

    #pragma unroll 4
    for (int c = 0; c < CB; c++) {
        float4 x0 = *(float4*)&Xs[c * 128 + pg * 8];
        float4 x1 = *(float4*)&Xs[c * 128 + pg * 8 + 4];
        #pragma unroll
        for (int r = 0; r < 6; r++) {
            float w = Ws[(og * 6 + r) * 96 + c];
            acc[r][0] += w * x0.x; acc[r][1] += w * x0.y;
            acc[r][2] += w * x0.z; acc[r][3] += w * x0.w;
            acc[r][4] += w * x1.x; acc[r][5] += w * x1.y;
            acc[r][6] += w * x1.z; acc[r][7] += w * x1.w;
        }
    }
    #pragma unroll
    for (int r = 0; r < 6; r++) {
        int o = og * 6 + r;
        float4 o0 = make_float4(acc[r][0], acc[r][1], acc[r][2], acc[r][3]);
        float4 o1 = make_float4(acc[r][4], acc[r][5], acc[r][6], acc[r][7]);
        *(float4*)&O[base + o * HW + pg * 8]     = o0;
        *(float4*)&O[base + o * HW + pg * 8 + 4] = o1;
    }
}

// ---------------- zero fold accumulators ---------------------------------------
__global__ void k_zero(float4* __restrict__ a, float4* __restrict__ b)
{
    int n = NELEM / 4;
    for (int i = blockIdx.x * blockDim.x + threadIdx.x; i < n;
         i += gridDim.x * blockDim.x) {
        a[i] = make_float4(0.f, 0.f, 0.f, 0.f);
        b[i] = make_float4(0.f, 0.f, 0.f, 0.f);
    }
}

// ---------------- window cross attention (both directions) ---------------------
// grid NWINDOWS, 256 thr, dyn smem 73728B
__global__ __launch_bounds__(256, 2)
void k_attn(const float* __restrict__ QL, const float* __restrict__ KL, const float* __restrict__ VL,
            const float* __restrict__ QH, const float* __restrict__ KH, const float* __restrict__ VH,
            float* __restrict__ accL, float* __restrict__ accH, int shift)
{
    extern __shared__ float sm[];
    float* Qs = sm;            // 96*64
    float* Ks = sm + 6144;
    float* Vs = sm + 12288;

    int win = blockIdx.x;
    int b = win / (NWIN * NWIN);
    int r = win - b * (NWIN * NWIN);
    int wi = r / NWIN, wj = r - wi * NWIN;
    int h0 = wi * 4, w0 = wj * 4;
    int tid = threadIdx.x;

    #pragma unroll 1
    for (int dir = 0; dir < 2; dir++) {
        const float* Qf = dir == 0 ? QL : QH;
        const float* Kf = dir == 0 ? KH : KL;
        const float* Vf = dir == 0 ? VH : VL;
        float* acc = dir == 0 ? accL : accH;

        // gather window (with optional cyclic shift for pass 2)
        for (int i = tid; i < 6144; i += 256) {
            int c = i >> 6, p = i & 63;
            int hh = (h0 + (p >> 3) + shift) & 127;
            int ww = (w0 + (p & 7) + shift) & 127;
            int gi = (b * CB + c) * HW + hh * 128 + ww;
            Qs[i] = Qf[gi]; Ks[i] = Kf[gi]; Vs[i] = Vf[gi];
        }
        __syncthreads();

        int head = tid >> 6, n = tid & 63;
        const float* Kh = Ks + head * 24 * 64;
        const float* Vh = Vs + head * 24 * 64;
        const float* Qh = Qs + head * 24 * 64;

        float q[24];
        #pragma unroll
        for (int d = 0; d < 24; d++) q[d] = Qh[d * 64 + n];

        float o[24];
        #pragma unroll
        for (int d = 0; d < 24; d++) o[d] = 0.f;
        float ssum = 0.f;

        for (int m = 0; m < 64; m++) {
            float s0 = 0.f, s1 = 0.f, s2 = 0.f, s3 = 0.f;
            #pragma unroll
            for (int d = 0; d < 24; d += 4) {
                s0 += q[d]     * Kh[d * 64 + m];
                s1 += q[d + 1] * Kh[(d + 1) * 64 + m];
                s2 += q[d + 2] * Kh[(d + 2) * 64 + m];
                s3 += q[d + 3] * Kh[(d + 3) * 64 + m];
            }
            float e = __expf(((s0 + s1) + (s2 + s3)) * ATT_SCALE);
            ssum += e;
            #pragma unroll
            for (int d = 0; d < 24; d++) o[d] += e * Vh[d * 64 + m];
        }
        float inv = 1.f / ssum;

        // scatter-add into fold accumulator (rolled coordinates; no wrap needed)
        int ph = n >> 3, pw = n & 7;
        int base = (b * CB + head * 24) * HW + (h0 + ph) * 128 + (w0 + pw);
        #pragma unroll
        for (int d = 0; d < 24; d++)
            atomicAdd(acc + base + d * HW, o[d] * inv);
        __syncthreads();
    }
}

// ---------------- fold/cnt + output projection + residual ----------------------
// dst = src + lnfield + W_proj * (fold(acc)/cnt)   [the _win return adds its own
// LN'd input, then the caller adds the pre-LN residual]
// grid (NB*H, 2), 256 thr, dyn smem 86528B
__global__ __launch_bounds__(256, 2)
void k_foldproj(const float* __restrict__ accL, const float* __restrict__ accH,
                const float* __restrict__ wpl, const float* __restrict__ wph,
                const float* __restrict__ srcL, const float* __restrict__ srcH,
                const float* __restrict__ lnL,  const float* __restrict__ lnH,
                float* __restrict__ dstL, float* __restrict__ dstH, int shift)
{
    extern __shared__ float sm[];
    float* Ws  = sm;            // 9216
    float* Xs  = sm + 9216;     // 12288
    float* rcw = sm + 21504;    // 128

    int t = blockIdx.y;
    const float* A   = t ? accH : accL;
    const float* W   = t ? wph  : wpl;
    const float* src = t ? srcH : srcL;
    const float* lnf = t ? lnH  : lnL;
    float*       dst = t ? dstH : dstL;

    int row = blockIdx.x;
    int b = row >> 7, h = row & 127;
    int hr = (h - shift) & 127;
    float invh = 1.f / cnt1f(hr);
    int tid = threadIdx.x;

    if (tid < 128) {
        int wr = (tid - shift) & 127;
        rcw[tid] = invh * (1.f / cnt1f(wr));
    }
    __syncthreads();

    int abase = b * CB * HW + hr * 128;
    for (int i = tid; i < 9216; i += 256) Ws[i] = W[i];
    for (int i = tid; i < 12288; i += 256) {
        int c = i >> 7, p = i & 127;
        int wr = (p - shift) & 127;
        Xs[i] = A[abase + c * HW + wr] * rcw[p];
    }
    __syncthreads();

    int og = tid >> 4, pg = tid & 15;
    float acc[6][8];
    #pragma unroll
    for (int r = 0; r < 6; r++)
        #pragma unroll
        for (int i = 0; i < 8; i++) acc[r][i] = 0.f;

    #pragma unroll 4
    for (int c = 0; c < CB; c++) {
        float4 x0 = *(float4*)&Xs[c * 128 + pg * 8];
        float4 x1 = *(float4*)&Xs[c * 128 + pg * 8 + 4];
        #pragma unroll
        for (int r = 0; r < 6; r++) {
            float w = Ws[(og * 6 + r) * 96 + c];
            acc[r][0] += w * x0.x; acc[r][1] += w * x0.y;
            acc[r][2] += w * x0.z; acc[r][3] += w * x0.w;
            acc[r][4] += w * x1.x; acc[r][5] += w * x1.y;
            acc[r][6] += w * x1.z; acc[r][7] += w * x1.w;
        }
    }
    int base = b * CB * HW + h * 128;
    #pragma unroll
    for (int r = 0; r < 6; r++) {
        int o = og * 6 + r;
        int off0 = base + o * HW + pg * 8;
        float4 s0 = *(const float4*)&src[off0];
        float4 s1 = *(const float4*)&src[off0 + 4];
        float4 n0 = *(const float4*)&lnf[off0];
        float4 n1 = *(const float4*)&lnf[off0 + 4];
        float4 o0 = make_float4(s0.x + n0.x + acc[r][0], s0.y + n0.y + acc[r][1],
                                s0.z + n0.z + acc[r][2], s0.w + n0.w + acc[r][3]);
        float4 o1 = make_float4(s1.x + n1.x + acc[r][4], s1.y + n1.y + acc[r][5],
                                s1.z + n1.z + acc[r][6], s1.w + n1.w + acc[r][7]);
        *(float4*)&dst[off0]     = o0;
        *(float4*)&dst[off0 + 4] = o1;
    }
}

// ---------------- MLP (96->384 gelu ->96) + residual, writes final output ------
// grid (NB*H, 2), 256 thr, dyn smem 135168B
__global__ __launch_bounds__(256, 1)
void k_mlp(const float* __restrict__ xL, const float* __restrict__ xH,
           const float* __restrict__ w1, const float* __restrict__ b1,
           const float* __restrict__ w2, const float* __restrict__ b2,
           float* __restrict__ outL, float* __restrict__ outH)
{
    extern __shared__ float sm[];
    float* Xs = sm;             // 12288
    float* Hs = sm + 12288;     // 12288
    float* Wc = sm + 24576;     // 9216

    const float* X = blockIdx.y ? xH : xL;
    float*       out = blockIdx.y ? outH : outL;
    int row = blockIdx.x;
    int b = row >> 7, h = row & 127;
    int base = b * CB * HW + h * 128;
    int tid = threadIdx.x;

    for (int i = tid; i < 12288; i += 256) {
        int c = i >> 7, p = i & 127;
        Xs[i] = X[base + c * HW + p];
    }

    int og = tid >> 4, pg = tid & 15;
    float acc[6][8];
    #pragma unroll
    for (int r = 0; r < 6; r++) {
        float bv = b2[og * 6 + r];
        #pragma unroll
        for (int i = 0; i < 8; i++) acc[r][i] = bv;
    }

    for (int k = 0; k < 4; k++) {
        __syncthreads();
        for (int i = tid; i < 9216; i += 256) Wc[i] = w1[k * 9216 + i];
        __syncthreads();

        float ha[6][8];
        #pragma unroll
        for (int r = 0; r < 6; r++)
            #pragma unroll
            for (int i = 0; i < 8; i++) ha[r][i] = 0.f;

        #pragma unroll 2
        for (int c = 0; c < CB; c++) {
            float4 x0 = *(float4*)&Xs[c * 128 + pg * 8];
            float4 x1 = *(float4*)&Xs[c * 128 + pg * 8 + 4];
            #pragma unroll
            for (int r = 0; r < 6; r++) {
                float w = Wc[(og * 6 + r) * 96 + c];
                ha[r][0] += w * x0.x; ha[r][1] += w * x0.y;
                ha[r][2] += w * x0.z; ha[r][3] += w * x0.w;
                ha[r][4] += w * x1.x; ha[r][5] += w * x1.y;
                ha[r][6] += w * x1.z; ha[r][7] += w * x1.w;
            }
        }
        #pragma unroll
        for (int r = 0; r < 6; r++) {
            float bb = b1[k * 96 + og * 6 + r];
            #pragma unroll
            for (int i = 0; i < 8; i++) {
                float v = ha[r][i] + bb;
                Hs[(og * 6 + r) * 128 + pg * 8 + i] =
                    0.5f * v * (1.f + erff(v * 0.70710678118654752f));
            }
        }
        __syncthreads();
        for (int i = tid; i < 9216; i += 256) {
            int o = i / 96, hl = i - o * 96;
            Wc[i] = w2[o * 384 + k * 96 + hl];
        }
        __syncthreads();

        #pragma unroll 2
        for (int c = 0; c < CB; c++) {
            float4 x0 = *(float4*)&Hs[c * 128 + pg * 8];
            float4 x1 = *(float4*)&Hs[c * 128 + pg * 8 + 4];
            #pragma unroll
            for (int r = 0; r < 6; r++) {
                float w = Wc[(og * 6 + r) * 96 + c];
                acc[r][0] += w * x0.x; acc[r][1] += w * x0.y;
                acc[r][2] += w * x0.z; acc[r][3] += w * x0.w;
                acc[r][4] += w * x1.x; acc[r][5] += w * x1.y;
                acc[r][6] += w * x1.z; acc[r][7] += w * x1.w;
            }
        }
    }

    #pragma unroll
    for (int r = 0; r < 6; r++) {
        int o = og * 6 + r;
        float4 x0 = *(float4*)&Xs[o * 128 + pg * 8];
        float4 x1 = *(float4*)&Xs[o * 128 + pg * 8 + 4];
        float4 o0 = make_float4(x0.x + acc[r][0], x0.y + acc[r][1],
                                x0.z + acc[r][2], x0.w + acc[r][3]);
        float4 o1 = make_float4(x1.x + acc[r][4], x1.y + acc[r][5],
                                x1.z + acc[r][6], x1.w + acc[r][7]);
        *(float4*)&out[base + o * HW + pg * 8]     = o0;
        *(float4*)&out[base + o * HW + pg * 8 + 4] = o1;
    }
}

// ---------------- host orchestration -------------------------------------------
static float* symaddr(const void* sym)
{
    void* p = nullptr;
    cudaGetSymbolAddress(&p, sym);
    return (float*)p;
}

extern "C" void kernel_launch(void* const* d_in, const int* in_sizes, int n_in,
                              void* d_out, int out_size)
{
    const float* low    = (const float*)d_in[0];
    const float* high   = (const float*)d_in[1];
    const float* ln1g   = (const float*)d_in[2];
    const float* ln1b   = (const float*)d_in[3];
    const float* ln2g   = (const float*)d_in[4];
    const float* ln2b   = (const float*)d_in[5];
    const float* se_w1  = (const float*)d_in[6];
    const float* se_w2  = (const float*)d_in[7];
    const float* wq_l   = (const float*)d_in[8];
    const float* wk_h   = (const float*)d_in[9];
    const float* wv_h   = (const float*)d_in[10];
    const float* wq_h   = (const float*)d_in[11];
    const float* wk_l   = (const float*)d_in[12];
    const float* wv_l   = (const float*)d_in[13];
    const float* wp_l   = (const float*)d_in[14];
    const float* wp_h   = (const float*)d_in[15];
    const float* mlp_w1 = (const float*)d_in[16];
    const float* mlp_b1 = (const float*)d_in[17];
    const float* mlp_w2 = (const float*)d_in[18];
    const float* mlp_b2 = (const float*)d_in[19];
    float* out = (float*)d_out;

    float* l1   = symaddr(g_l1);    float* h1   = symaddr(g_h1);
    float* QL   = symaddr(g_QL);    float* KL   = symaddr(g_KL);  float* VL = symaddr(g_VL);
    float* QH   = symaddr(g_QH);    float* KH   = symaddr(g_KH);  float* VH = symaddr(g_VH);
    float* accL = symaddr(g_accL);  float* accH = symaddr(g_accH);
    float* low1 = symaddr(g_low1);  float* high1 = symaddr(g_high1);
    float* low2 = symaddr(g_low2);  float* high2 = symaddr(g_high2);
    float* pool = symaddr(g_pool);  float* se    = symaddr(g_se);

    cudaFuncSetAttribute(k_ln,       cudaFuncAttributeMaxDynamicSharedMemorySize, 50176);
    cudaFuncSetAttribute(k_proj6,    cudaFuncAttributeMaxDynamicSharedMemorySize, 86016);
    cudaFuncSetAttribute(k_attn,     cudaFuncAttributeMaxDynamicSharedMemorySize, 73728);
    cudaFuncSetAttribute(k_foldproj, cudaFuncAttributeMaxDynamicSharedMemorySize, 86528);
    cudaFuncSetAttribute(k_mlp,      cudaFuncAttributeMaxDynamicSharedMemorySize, 135168);

    dim3 gRow2(NB * HWIMG, 2);
    dim3 gProj(NB * HWIMG, 6);

    // ---------------- pass 1 (shift = 0, ln1) ----------------
    k_ln<<<gRow2, 256, 50176>>>(low, high, ln1g, ln1b, l1, h1);
    k_pool<<<NB * CB, 256>>>(h1, pool);
    k_se<<<1, 256>>>(pool, se_w1, se_w2, se);
    k_proj6<<<gProj, 256, 86016>>>(l1, h1, se, wq_l, wk_l, wv_l, wq_h, wk_h, wv_h,
                                   QL, KL, VL, QH, KH, VH);
    k_zero<<<1024, 256>>>((float4*)accL, (float4*)accH);
    k_attn<<<NWINDOWS, 256, 73728>>>(QL, KL, VL, QH, KH, VH, accL, accH, 0);
    k_foldproj<<<gRow2, 256, 86528>>>(accL, accH, wp_l, wp_h, low, high, l1, h1,
                                      low1, high1, 0);

    // ---------------- pass 2 (shift = 4, ln2) ----------------
    k_ln<<<gRow2, 256, 50176>>>(low1, high1, ln2g, ln2b, l1, h1);
    k_pool<<<NB * CB, 256>>>(h1, pool);
    k_se<<<1, 256>>>(pool, se_w1, se_w2, se);
    k_proj6<<<gProj, 256, 86016>>>(l1, h1, se, wq_l, wk_l, wv_l, wq_h, wk_h, wv_h,
                                   QL, KL, VL, QH, KH, VH);
    k_zero<<<1024, 256>>>((float4*)accL, (float4*)accH);
    k_attn<<<NWINDOWS, 256, 73728>>>(QL, KL, VL, QH, KH, VH, accL, accH, 4);
    k_foldproj<<<gRow2, 256, 86528>>>(accL, accH, wp_l, wp_h, low1, high1, l1, h1,
                                      low2, high2, 4);

    // ---------------- MLP + residual -> output ----------------
    k_mlp<<<gRow2, 256, 135168>>>(low2, high2, mlp_w1, mlp_b1, mlp_w2, mlp_b2,
                                  out, out + NELEM);
}

// round 5
// speedup vs baseline: 1.1821x; 1.1821x over previous
#include <cuda_runtime.h>
#include <math.h>

#define CB     96
#define HWIMG  128
#define HW     16384          // 128*128
#define NB     2
#define NELEM  3145728        // NB*CB*HW
#define NWIN   31
#define NWINDOWS 1922         // NB*31*31
#define ATT_SCALE 0.20412414523193154f  // 1/sqrt(24)

typedef unsigned long long ull;

// ---------------- packed f32x2 helpers (sm_103a FFMA2) --------------------------
__device__ __forceinline__ ull pk2(float lo, float hi) {
    ull r; asm("mov.b64 %0,{%1,%2};" : "=l"(r) : "f"(lo), "f"(hi)); return r;
}
__device__ __forceinline__ void upk(ull v, float& lo, float& hi) {
    asm("mov.b64 {%0,%1},%2;" : "=f"(lo), "=f"(hi) : "l"(v));
}
__device__ __forceinline__ void ffma2(ull& d, ull a, ull b) {
    asm("fma.rn.f32x2 %0,%1,%2,%0;" : "+l"(d) : "l"(a), "l"(b));
}
__device__ __forceinline__ ull fadd2(ull a, ull b) {
    ull r; asm("add.rn.f32x2 %0,%1,%2;" : "=l"(r) : "l"(a), "l"(b)); return r;
}

// ---------------- scratch (static device globals; alloc-free rule) -------------
__device__ float g_l1[NELEM], g_h1[NELEM];
__device__ float g_QL[NELEM], g_KL[NELEM], g_VL[NELEM];
__device__ float g_QH[NELEM], g_KH[NELEM], g_VH[NELEM];
__device__ float g_accL[NELEM], g_accH[NELEM];
__device__ float g_low1[NELEM], g_high1[NELEM];
__device__ float g_low2[NELEM], g_high2[NELEM];
__device__ float g_pool[NB*CB], g_se[NB*CB];

// ---------------- helpers ------------------------------------------------------
__device__ __forceinline__ float cnt1f(int h) {
    int imin = (h <= 7) ? 0 : ((h - 4) >> 2);
    int imax = min(30, h >> 2);
    return (float)(imax - imin + 1);
}

__device__ __forceinline__ float gelu_f(float v) {
    // tanh-form gelu; |err| <= 3e-4 abs vs exact, <<1e-5 for |v|<1
    float u = 0.7978845608028654f * (v + 0.044715f * v * v * v);
    float t = 1.f - 2.f / (__expf(2.f * u) + 1.f);
    return 0.5f * v * (1.f + t);
}

// ---------------- LN over channel axis, per pixel ------------------------------
__global__ void k_ln(const float* __restrict__ srcL, const float* __restrict__ srcH,
                     const float* __restrict__ gw,  const float* __restrict__ bw,
                     float* __restrict__ dstL, float* __restrict__ dstH)
{
    extern __shared__ float sm[];
    float* Xs = sm;              // 96*128
    float* mu = sm + 12288;
    float* rv = sm + 12416;
    const float* src = blockIdx.y ? srcH : srcL;
    float*       dst = blockIdx.y ? dstH : dstL;
    int row = blockIdx.x;
    int b = row >> 7, h = row & 127;
    int base = b * CB * HW + h * 128;
    int tid = threadIdx.x;

    for (int i = tid; i < 12288; i += 256) {
        int c = i >> 7, p = i & 127;
        Xs[i] = src[base + c * HW + p];
    }
    __syncthreads();
    if (tid < 128) {
        float s = 0.f, s2 = 0.f;
        #pragma unroll 8
        for (int c = 0; c < CB; c++) {
            float v = Xs[c * 128 + tid];
            s += v; s2 += v * v;
        }
        float m = s * (1.f / 96.f);
        float var = s2 * (1.f / 96.f) - m * m;
        mu[tid] = m;
        rv[tid] = rsqrtf(var + 1e-5f);
    }
    __syncthreads();
    for (int i = tid; i < 12288; i += 256) {
        int c = i >> 7, p = i & 127;
        dst[base + c * HW + p] = (Xs[i] - mu[p]) * rv[p] * gw[c] + bw[c];
    }
}

// ---------------- SE: spatial mean pool per (b,c) ------------------------------
__global__ void k_pool(const float* __restrict__ h1, float* __restrict__ pool)
{
    int bc = blockIdx.x;
    const float* p = h1 + bc * HW;
    float s = 0.f;
    for (int i = threadIdx.x; i < HW; i += 256) s += p[i];
    __shared__ float red[256];
    red[threadIdx.x] = s; __syncthreads();
    for (int o = 128; o > 0; o >>= 1) {
        if (threadIdx.x < o) red[threadIdx.x] += red[threadIdx.x + o];
        __syncthreads();
    }
    if (threadIdx.x == 0) pool[bc] = red[0] * (1.f / 16384.f);
}

// ---------------- SE: FC -> relu -> FC -> sigmoid ------------------------------
__global__ void k_se(const float* __restrict__ pool, const float* __restrict__ w1,
                     const float* __restrict__ w2, float* __restrict__ se)
{
    int t = threadIdx.x;
    if (t >= NB * CB) return;
    int b = t / CB, c = t % CB;
    int gi = c >> 5, j = c & 31;
    const float* pl = pool + b * CB + gi * 32;
    float z0 = 0.f, z1 = 0.f;
    #pragma unroll
    for (int g = 0; g < 32; g++) {
        float pv = pl[g];
        z0 += pv * w1[gi * 64 + g];
        z1 += pv * w1[gi * 64 + 32 + g];
    }
    z0 = fmaxf(z0, 0.f); z1 = fmaxf(z1, 0.f);
    float a = z0 * w2[gi * 64 + j * 2] + z1 * w2[gi * 64 + j * 2 + 1];
    se[t] = 1.f / (1.f + __expf(-a));
}

// ---------------- 6 per-pixel projections (96x96 GEMMs, FFMA2) -----------------
__global__ __launch_bounds__(256, 2)
void k_proj6(const float* __restrict__ l1, const float* __restrict__ h1,
             const float* __restrict__ se,
             const float* __restrict__ Wql, const float* __restrict__ Wkl, const float* __restrict__ Wvl,
             const float* __restrict__ Wqh, const float* __restrict__ Wkh, const float* __restrict__ Wvh,
             float* __restrict__ QL, float* __restrict__ KL, float* __restrict__ VL,
             float* __restrict__ QH, float* __restrict__ KH, float* __restrict__ VH)
{
    extern __shared__ float sm[];
    float* Ws = sm;           // 9216
    float* Xs = sm + 9216;    // 12288
    int row = blockIdx.x;
    int j = blockIdx.y;
    const float* W; const float* X; float* O; bool useSE;
    switch (j) {
        case 0: W = Wql; X = l1; O = QL; useSE = false; break;
        case 1: W = Wkl; X = l1; O = KL; useSE = false; break;
        case 2: W = Wvl; X = l1; O = VL; useSE = false; break;
        case 3: W = Wqh; X = h1; O = QH; useSE = true;  break;
        case 4: W = Wkh; X = h1; O = KH; useSE = true;  break;
        default: W = Wvh; X = h1; O = VH; useSE = true; break;
    }
    int b = row >> 7, h = row & 127;
    int base = b * CB * HW + h * 128;
    int tid = threadIdx.x;

    for (int i = tid; i < 9216; i += 256) Ws[i] = W[i];
    for (int i = tid; i < 12288; i += 256) {
        int c = i >> 7, p = i & 127;
        float v = X[base + c * HW + p];
        if (useSE) v *= se[b * CB + c];
        Xs[i] = v;
    }
    __syncthreads();

    int og = tid >> 4, pg = tid & 15;
    ull acc[6][4];
    #pragma unroll
    for (int r = 0; r < 6; r++)
        #pragma unroll
        for (int i = 0; i < 4; i++) acc[r][i] = 0ull;

    #pragma unroll 4
    for (int c = 0; c < CB; c++) {
        ulonglong2 xa = *(const ulonglong2*)&Xs[c * 128 + pg * 8];
        ulonglong2 xb = *(const ulonglong2*)&Xs[c * 128 + pg * 8 + 4];
        #pragma unroll
        for (int r = 0; r < 6; r++) {
            float w = Ws[(og * 6 + r) * 96 + c];
            ull ww = pk2(w, w);
            ffma2(acc[r][0], ww, xa.x); ffma2(acc[r][1], ww, xa.y);
            ffma2(acc[r][2], ww, xb.x); ffma2(acc[r][3], ww, xb.y);
        }
    }
    #pragma unroll
    for (int r = 0; r < 6; r++) {
        int o = og * 6 + r;
        *(ulonglong2*)&O[base + o * HW + pg * 8]     = make_ulonglong2(acc[r][0], acc[r][1]);
        *(ulonglong2*)&O[base + o * HW + pg * 8 + 4] = make_ulonglong2(acc[r][2], acc[r][3]);
    }
}

// ---------------- zero fold accumulators ---------------------------------------
__global__ void k_zero(float4* __restrict__ a, float4* __restrict__ b)
{
    int n = NELEM / 4;
    for (int i = blockIdx.x * blockDim.x + threadIdx.x; i < n;
         i += gridDim.x * blockDim.x) {
        a[i] = make_float4(0.f, 0.f, 0.f, 0.f);
        b[i] = make_float4(0.f, 0.f, 0.f, 0.f);
    }
}

// ---------------- window cross attention (FFMA2, transposed K/V) ---------------
// grid NWINDOWS, 256 thr, dyn smem 73728B
__global__ __launch_bounds__(256, 2)
void k_attn(const float* __restrict__ QL, const float* __restrict__ KL, const float* __restrict__ VL,
            const float* __restrict__ QH, const float* __restrict__ KH, const float* __restrict__ VH,
            float* __restrict__ accL, float* __restrict__ accH, int shift)
{
    extern __shared__ float sm[];
    float* Qs = sm;            // [96][64]            6144
    float* Kt = sm + 6144;     // [4][64][24] m-major 6144
    float* Vt = sm + 12288;    // [4][64][24]         6144

    int win = blockIdx.x;
    int b = win / (NWIN * NWIN);
    int r = win - b * (NWIN * NWIN);
    int wi = r / NWIN, wj = r - wi * NWIN;
    int h0 = wi * 4, w0 = wj * 4;
    int tid = threadIdx.x;

    #pragma unroll 1
    for (int dir = 0; dir < 2; dir++) {
        const float* Qf = dir == 0 ? QL : QH;
        const float* Kf = dir == 0 ? KH : KL;
        const float* Vf = dir == 0 ? VH : VL;
        float* acc = dir == 0 ? accL : accH;

        for (int i = tid; i < 6144; i += 256) {
            int c = i >> 6, p = i & 63;
            int hh = (h0 + (p >> 3) + shift) & 127;
            int ww = (w0 + (p & 7) + shift) & 127;
            int gi = (b * CB + c) * HW + hh * 128 + ww;
            int hd = c / 24, d = c - hd * 24;
            int ti = hd * 1536 + p * 24 + d;
            Qs[i] = Qf[gi];
            Kt[ti] = Kf[gi];
            Vt[ti] = Vf[gi];
        }
        __syncthreads();

        int head = tid >> 6, n = tid & 63;
        const float* Qh = Qs + head * 24 * 64;
        const ull* Kb = (const ull*)(Kt + head * 1536);
        const ull* Vb = (const ull*)(Vt + head * 1536);

        ull qp[12];
        #pragma unroll
        for (int jj = 0; jj < 12; jj++)
            qp[jj] = pk2(Qh[(2 * jj) * 64 + n], Qh[(2 * jj + 1) * 64 + n]);

        ull op[12];
        #pragma unroll
        for (int jj = 0; jj < 12; jj++) op[jj] = 0ull;
        float ssum = 0.f;

        for (int m = 0; m < 64; m++) {
            const ull* Kp = Kb + m * 12;
            ull s = 0ull;
            #pragma unroll
            for (int jj = 0; jj < 12; jj++) ffma2(s, qp[jj], Kp[jj]);
            float slo, shi; upk(s, slo, shi);
            float e = __expf((slo + shi) * ATT_SCALE);
            ssum += e;
            ull ee = pk2(e, e);
            const ull* Vp = Vb + m * 12;
            #pragma unroll
            for (int jj = 0; jj < 12; jj++) ffma2(op[jj], ee, Vp[jj]);
        }
        float inv = 1.f / ssum;

        int ph = n >> 3, pw = n & 7;
        int base = (b * CB + head * 24) * HW + (h0 + ph) * 128 + (w0 + pw);
        #pragma unroll
        for (int jj = 0; jj < 12; jj++) {
            float lo, hi; upk(op[jj], lo, hi);
            atomicAdd(acc + base + (2 * jj) * HW,     lo * inv);
            atomicAdd(acc + base + (2 * jj + 1) * HW, hi * inv);
        }
        __syncthreads();
    }
}

// ---------------- fold/cnt + output projection + residual (FFMA2) --------------
// dst = src + lnfield + W_proj * (fold(acc)/cnt)
__global__ __launch_bounds__(256, 2)
void k_foldproj(const float* __restrict__ accL, const float* __restrict__ accH,
                const float* __restrict__ wpl, const float* __restrict__ wph,
                const float* __restrict__ srcL, const float* __restrict__ srcH,
                const float* __restrict__ lnL,  const float* __restrict__ lnH,
                float* __restrict__ dstL, float* __restrict__ dstH, int shift)
{
    extern __shared__ float sm[];
    float* Ws  = sm;            // 9216
    float* Xs  = sm + 9216;     // 12288
    float* rcw = sm + 21504;    // 128

    int t = blockIdx.y;
    const float* A   = t ? accH : accL;
    const float* W   = t ? wph  : wpl;
    const float* src = t ? srcH : srcL;
    const float* lnf = t ? lnH  : lnL;
    float*       dst = t ? dstH : dstL;

    int row = blockIdx.x;
    int b = row >> 7, h = row & 127;
    int hr = (h - shift) & 127;
    float invh = 1.f / cnt1f(hr);
    int tid = threadIdx.x;

    if (tid < 128) {
        int wr = (tid - shift) & 127;
        rcw[tid] = invh * (1.f / cnt1f(wr));
    }
    __syncthreads();

    int abase = b * CB * HW + hr * 128;
    for (int i = tid; i < 9216; i += 256) Ws[i] = W[i];
    for (int i = tid; i < 12288; i += 256) {
        int c = i >> 7, p = i & 127;
        int wr = (p - shift) & 127;
        Xs[i] = A[abase + c * HW + wr] * rcw[p];
    }
    __syncthreads();

    int og = tid >> 4, pg = tid & 15;
    ull acc[6][4];
    #pragma unroll
    for (int r = 0; r < 6; r++)
        #pragma unroll
        for (int i = 0; i < 4; i++) acc[r][i] = 0ull;

    #pragma unroll 4
    for (int c = 0; c < CB; c++) {
        ulonglong2 xa = *(const ulonglong2*)&Xs[c * 128 + pg * 8];
        ulonglong2 xb = *(const ulonglong2*)&Xs[c * 128 + pg * 8 + 4];
        #pragma unroll
        for (int r = 0; r < 6; r++) {
            float w = Ws[(og * 6 + r) * 96 + c];
            ull ww = pk2(w, w);
            ffma2(acc[r][0], ww, xa.x); ffma2(acc[r][1], ww, xa.y);
            ffma2(acc[r][2], ww, xb.x); ffma2(acc[r][3], ww, xb.y);
        }
    }
    int base = b * CB * HW + h * 128;
    #pragma unroll
    for (int r = 0; r < 6; r++) {
        int o = og * 6 + r;
        int off0 = base + o * HW + pg * 8;
        ulonglong2 s0 = *(const ulonglong2*)&src[off0];
        ulonglong2 s1 = *(const ulonglong2*)&src[off0 + 4];
        ulonglong2 n0 = *(const ulonglong2*)&lnf[off0];
        ulonglong2 n1 = *(const ulonglong2*)&lnf[off0 + 4];
        ulonglong2 o0 = make_ulonglong2(fadd2(fadd2(s0.x, n0.x), acc[r][0]),
                                        fadd2(fadd2(s0.y, n0.y), acc[r][1]));
        ulonglong2 o1 = make_ulonglong2(fadd2(fadd2(s1.x, n1.x), acc[r][2]),
                                        fadd2(fadd2(s1.y, n1.y), acc[r][3]));
        *(ulonglong2*)&dst[off0]     = o0;
        *(ulonglong2*)&dst[off0 + 4] = o1;
    }
}

// ---------------- MLP (96->384 gelu ->96) + residual (FFMA2) -------------------
__global__ __launch_bounds__(256, 1)
void k_mlp(const float* __restrict__ xL, const float* __restrict__ xH,
           const float* __restrict__ w1, const float* __restrict__ b1,
           const float* __restrict__ w2, const float* __restrict__ b2,
           float* __restrict__ outL, float* __restrict__ outH)
{
    extern __shared__ float sm[];
    float* Xs = sm;             // 12288
    float* Hs = sm + 12288;     // 12288
    float* Wc = sm + 24576;     // 9216

    const float* X = blockIdx.y ? xH : xL;
    float*       out = blockIdx.y ? outH : outL;
    int row = blockIdx.x;
    int b = row >> 7, h = row & 127;
    int base = b * CB * HW + h * 128;
    int tid = threadIdx.x;

    for (int i = tid; i < 12288; i += 256) {
        int c = i >> 7, p = i & 127;
        Xs[i] = X[base + c * HW + p];
    }

    int og = tid >> 4, pg = tid & 15;
    ull acc[6][4];
    #pragma unroll
    for (int r = 0; r < 6; r++) {
        float bv = b2[og * 6 + r];
        ull bp = pk2(bv, bv);
        #pragma unroll
        for (int i = 0; i < 4; i++) acc[r][i] = bp;
    }

    for (int k = 0; k < 4; k++) {
        __syncthreads();
        for (int i = tid; i < 9216; i += 256) Wc[i] = w1[k * 9216 + i];
        __syncthreads();

        ull ha[6][4];
        #pragma unroll
        for (int r = 0; r < 6; r++)
            #pragma unroll
            for (int i = 0; i < 4; i++) ha[r][i] = 0ull;

        #pragma unroll 2
        for (int c = 0; c < CB; c++) {
            ulonglong2 xa = *(const ulonglong2*)&Xs[c * 128 + pg * 8];
            ulonglong2 xb = *(const ulonglong2*)&Xs[c * 128 + pg * 8 + 4];
            #pragma unroll
            for (int r = 0; r < 6; r++) {
                float w = Wc[(og * 6 + r) * 96 + c];
                ull ww = pk2(w, w);
                ffma2(ha[r][0], ww, xa.x); ffma2(ha[r][1], ww, xa.y);
                ffma2(ha[r][2], ww, xb.x); ffma2(ha[r][3], ww, xb.y);
            }
        }
        #pragma unroll
        for (int r = 0; r < 6; r++) {
            float bb = b1[k * 96 + og * 6 + r];
            float v[8];
            upk(ha[r][0], v[0], v[1]); upk(ha[r][1], v[2], v[3]);
            upk(ha[r][2], v[4], v[5]); upk(ha[r][3], v[6], v[7]);
            float g[8];
            #pragma unroll
            for (int i = 0; i < 8; i++) g[i] = gelu_f(v[i] + bb);
            *(float4*)&Hs[(og * 6 + r) * 128 + pg * 8]     = make_float4(g[0], g[1], g[2], g[3]);
            *(float4*)&Hs[(og * 6 + r) * 128 + pg * 8 + 4] = make_float4(g[4], g[5], g[6], g[7]);
        }
        __syncthreads();
        for (int i = tid; i < 9216; i += 256) {
            int o = i / 96, hl = i - o * 96;
            Wc[i] = w2[o * 384 + k * 96 + hl];
        }
        __syncthreads();

        #pragma unroll 2
        for (int c = 0; c < CB; c++) {
            ulonglong2 xa = *(const ulonglong2*)&Hs[c * 128 + pg * 8];
            ulonglong2 xb = *(const ulonglong2*)&Hs[c * 128 + pg * 8 + 4];
            #pragma unroll
            for (int r = 0; r < 6; r++) {
                float w = Wc[(og * 6 + r) * 96 + c];
                ull ww = pk2(w, w);
                ffma2(acc[r][0], ww, xa.x); ffma2(acc[r][1], ww, xa.y);
                ffma2(acc[r][2], ww, xb.x); ffma2(acc[r][3], ww, xb.y);
            }
        }
    }

    #pragma unroll
    for (int r = 0; r < 6; r++) {
        int o = og * 6 + r;
        ulonglong2 xa = *(const ulonglong2*)&Xs[o * 128 + pg * 8];
        ulonglong2 xb = *(const ulonglong2*)&Xs[o * 128 + pg * 8 + 4];
        ulonglong2 o0 = make_ulonglong2(fadd2(xa.x, acc[r][0]), fadd2(xa.y, acc[r][1]));
        ulonglong2 o1 = make_ulonglong2(fadd2(xb.x, acc[r][2]), fadd2(xb.y, acc[r][3]));
        *(ulonglong2*)&out[base + o * HW + pg * 8]     = o0;
        *(ulonglong2*)&out[base + o * HW + pg * 8 + 4] = o1;
    }
}

// ---------------- host orchestration -------------------------------------------
static float* symaddr(const void* sym)
{
    void* p = nullptr;
    cudaGetSymbolAddress(&p, sym);
    return (float*)p;
}

extern "C" void kernel_launch(void* const* d_in, const int* in_sizes, int n_in,
                              void* d_out, int out_size)
{
    const float* low    = (const float*)d_in[0];
    const float* high   = (const float*)d_in[1];
    const float* ln1g   = (const float*)d_in[2];
    const float* ln1b   = (const float*)d_in[3];
    const float* ln2g   = (const float*)d_in[4];
    const float* ln2b   = (const float*)d_in[5];
    const float* se_w1  = (const float*)d_in[6];
    const float* se_w2  = (const float*)d_in[7];
    const float* wq_l   = (const float*)d_in[8];
    const float* wk_h   = (const float*)d_in[9];
    const float* wv_h   = (const float*)d_in[10];
    const float* wq_h   = (const float*)d_in[11];
    const float* wk_l   = (const float*)d_in[12];
    const float* wv_l   = (const float*)d_in[13];
    const float* wp_l   = (const float*)d_in[14];
    const float* wp_h   = (const float*)d_in[15];
    const float* mlp_w1 = (const float*)d_in[16];
    const float* mlp_b1 = (const float*)d_in[17];
    const float* mlp_w2 = (const float*)d_in[18];
    const float* mlp_b2 = (const float*)d_in[19];
    float* out = (float*)d_out;

    float* l1   = symaddr(g_l1);    float* h1   = symaddr(g_h1);
    float* QL   = symaddr(g_QL);    float* KL   = symaddr(g_KL);  float* VL = symaddr(g_VL);
    float* QH   = symaddr(g_QH);    float* KH   = symaddr(g_KH);  float* VH = symaddr(g_VH);
    float* accL = symaddr(g_accL);  float* accH = symaddr(g_accH);
    float* low1 = symaddr(g_low1);  float* high1 = symaddr(g_high1);
    float* low2 = symaddr(g_low2);  float* high2 = symaddr(g_high2);
    float* pool = symaddr(g_pool);  float* se    = symaddr(g_se);

    cudaFuncSetAttribute(k_ln,       cudaFuncAttributeMaxDynamicSharedMemorySize, 50176);
    cudaFuncSetAttribute(k_proj6,    cudaFuncAttributeMaxDynamicSharedMemorySize, 86016);
    cudaFuncSetAttribute(k_attn,     cudaFuncAttributeMaxDynamicSharedMemorySize, 73728);
    cudaFuncSetAttribute(k_foldproj, cudaFuncAttributeMaxDynamicSharedMemorySize, 86528);
    cudaFuncSetAttribute(k_mlp,      cudaFuncAttributeMaxDynamicSharedMemorySize, 135168);

    dim3 gRow2(NB * HWIMG, 2);
    dim3 gProj(NB * HWIMG, 6);

    // ---------------- pass 1 (shift = 0, ln1) ----------------
    k_ln<<<gRow2, 256, 50176>>>(low, high, ln1g, ln1b, l1, h1);
    k_pool<<<NB * CB, 256>>>(h1, pool);
    k_se<<<1, 256>>>(pool, se_w1, se_w2, se);
    k_proj6<<<gProj, 256, 86016>>>(l1, h1, se, wq_l, wk_l, wv_l, wq_h, wk_h, wv_h,
                                   QL, KL, VL, QH, KH, VH);
    k_zero<<<1024, 256>>>((float4*)accL, (float4*)accH);
    k_attn<<<NWINDOWS, 256, 73728>>>(QL, KL, VL, QH, KH, VH, accL, accH, 0);
    k_foldproj<<<gRow2, 256, 86528>>>(accL, accH, wp_l, wp_h, low, high, l1, h1,
                                      low1, high1, 0);

    // ---------------- pass 2 (shift = 4, ln2) ----------------
    k_ln<<<gRow2, 256, 50176>>>(low1, high1, ln2g, ln2b, l1, h1);
    k_pool<<<NB * CB, 256>>>(h1, pool);
    k_se<<<1, 256>>>(pool, se_w1, se_w2, se);
    k_proj6<<<gProj, 256, 86016>>>(l1, h1, se, wq_l, wk_l, wv_l, wq_h, wk_h, wv_h,
                                   QL, KL, VL, QH, KH, VH);
    k_zero<<<1024, 256>>>((float4*)accL, (float4*)accH);
    k_attn<<<NWINDOWS, 256, 73728>>>(QL, KL, VL, QH, KH, VH, accL, accH, 4);
    k_foldproj<<<gRow2, 256, 86528>>>(accL, accH, wp_l, wp_h, low1, high1, l1, h1,
                                      low2, high2, 4);

    // ---------------- MLP + residual -> output ----------------
    k_mlp<<<gRow2, 256, 135168>>>(low2, high2, mlp_w1, mlp_b1, mlp_w2, mlp_b2,
                                  out, out + NELEM);
}

// round 7
// speedup vs baseline: 1.2120x; 1.0253x over previous
#include <cuda_runtime.h>
#include <math.h>

#define CB     96
#define HWIMG  128
#define HW     16384          // 128*128
#define NB     2
#define NELEM  3145728        // NB*CB*HW
#define NWIN   31
#define NWINDOWS 1922         // NB*31*31
#define ATT_SCALE 0.20412414523193154f  // 1/sqrt(24)

typedef unsigned long long ull;

// ---------------- packed f32x2 helpers (sm_103a FFMA2) --------------------------
__device__ __forceinline__ ull pk2(float lo, float hi) {
    ull r; asm("mov.b64 %0,{%1,%2};" : "=l"(r) : "f"(lo), "f"(hi)); return r;
}
__device__ __forceinline__ void upk(ull v, float& lo, float& hi) {
    asm("mov.b64 {%0,%1},%2;" : "=f"(lo), "=f"(hi) : "l"(v));
}
__device__ __forceinline__ void ffma2(ull& d, ull a, ull b) {
    asm("fma.rn.f32x2 %0,%1,%2,%0;" : "+l"(d) : "l"(a), "l"(b));
}
__device__ __forceinline__ ull fadd2(ull a, ull b) {
    ull r; asm("add.rn.f32x2 %0,%1,%2;" : "=l"(r) : "l"(a), "l"(b)); return r;
}

// ---------------- scratch (static device globals; alloc-free rule) -------------
__device__ float g_l1[NELEM], g_h1[NELEM];
__device__ float g_QL[NELEM], g_KL[NELEM], g_VL[NELEM];
__device__ float g_QH[NELEM], g_KH[NELEM], g_VH[NELEM];
__device__ float g_accL[NELEM], g_accH[NELEM];
__device__ float g_low1[NELEM], g_high1[NELEM];
__device__ float g_low2[NELEM], g_high2[NELEM];
__device__ float g_pool[NB*CB], g_se[NB*CB];

// ---------------- helpers ------------------------------------------------------
__device__ __forceinline__ float cnt1f(int h) {
    int imin = (h <= 7) ? 0 : ((h - 4) >> 2);
    int imax = min(30, h >> 2);
    return (float)(imax - imin + 1);
}

__device__ __forceinline__ float gelu_f(float v) {
    float u = 0.7978845608028654f * (v + 0.044715f * v * v * v);
    float t = 1.f - 2.f / (__expf(2.f * u) + 1.f);
    return 0.5f * v * (1.f + t);
}

// 6-row x 8-px FFMA2 micro-tile over 96 c's with vectorized weight loads.
// Ws rows must be 96-float, c-contiguous; Xs is [96][128].
__device__ __forceinline__ void gemm6x8(const float* __restrict__ Ws,
                                        const float* __restrict__ Xs,
                                        int og, int pg, ull acc[6][4])
{
    #pragma unroll 1
    for (int c4 = 0; c4 < CB; c4 += 4) {
        float4 wv[6];
        #pragma unroll
        for (int r = 0; r < 6; r++)
            wv[r] = *(const float4*)&Ws[(og * 6 + r) * 96 + c4];
        #pragma unroll
        for (int cc = 0; cc < 4; cc++) {
            const float* xp = &Xs[(c4 + cc) * 128 + pg * 8];
            ulonglong2 xa = *(const ulonglong2*)xp;
            ulonglong2 xb = *(const ulonglong2*)(xp + 4);
            #pragma unroll
            for (int r = 0; r < 6; r++) {
                float w = cc == 0 ? wv[r].x : cc == 1 ? wv[r].y
                        : cc == 2 ? wv[r].z : wv[r].w;
                ull ww = pk2(w, w);
                ffma2(acc[r][0], ww, xa.x); ffma2(acc[r][1], ww, xa.y);
                ffma2(acc[r][2], ww, xb.x); ffma2(acc[r][3], ww, xb.y);
            }
        }
    }
}

// ---------------- LN over channel axis, per pixel ------------------------------
__global__ void k_ln(const float* __restrict__ srcL, const float* __restrict__ srcH,
                     const float* __restrict__ gw,  const float* __restrict__ bw,
                     float* __restrict__ dstL, float* __restrict__ dstH)
{
    extern __shared__ float sm[];
    float* Xs = sm;              // 96*128
    float* mu = sm + 12288;
    float* rv = sm + 12416;
    const float* src = blockIdx.y ? srcH : srcL;
    float*       dst = blockIdx.y ? dstH : dstL;
    int row = blockIdx.x;
    int b = row >> 7, h = row & 127;
    int base = b * CB * HW + h * 128;
    int tid = threadIdx.x;

    for (int i = tid; i < 12288; i += 256) {
        int c = i >> 7, p = i & 127;
        Xs[i] = src[base + c * HW + p];
    }
    __syncthreads();
    if (tid < 128) {
        float s = 0.f, s2 = 0.f;
        #pragma unroll 8
        for (int c = 0; c < CB; c++) {
            float v = Xs[c * 128 + tid];
            s += v; s2 += v * v;
        }
        float m = s * (1.f / 96.f);
        float var = s2 * (1.f / 96.f) - m * m;
        mu[tid] = m;
        rv[tid] = rsqrtf(var + 1e-5f);
    }
    __syncthreads();
    for (int i = tid; i < 12288; i += 256) {
        int c = i >> 7, p = i & 127;
        dst[base + c * HW + p] = (Xs[i] - mu[p]) * rv[p] * gw[c] + bw[c];
    }
}

// ---------------- SE: spatial mean pool per (b,c) ------------------------------
__global__ void k_pool(const float* __restrict__ h1, float* __restrict__ pool)
{
    int bc = blockIdx.x;
    const float* p = h1 + bc * HW;
    float s = 0.f;
    for (int i = threadIdx.x; i < HW; i += 256) s += p[i];
    __shared__ float red[256];
    red[threadIdx.x] = s; __syncthreads();
    for (int o = 128; o > 0; o >>= 1) {
        if (threadIdx.x < o) red[threadIdx.x] += red[threadIdx.x + o];
        __syncthreads();
    }
    if (threadIdx.x == 0) pool[bc] = red[0] * (1.f / 16384.f);
}

// ---------------- SE: FC -> relu -> FC -> sigmoid ------------------------------
__global__ void k_se(const float* __restrict__ pool, const float* __restrict__ w1,
                     const float* __restrict__ w2, float* __restrict__ se)
{
    int t = threadIdx.x;
    if (t >= NB * CB) return;
    int b = t / CB, c = t % CB;
    int gi = c >> 5, j = c & 31;
    const float* pl = pool + b * CB + gi * 32;
    float z0 = 0.f, z1 = 0.f;
    #pragma unroll
    for (int g = 0; g < 32; g++) {
        float pv = pl[g];
        z0 += pv * w1[gi * 64 + g];
        z1 += pv * w1[gi * 64 + 32 + g];
    }
    z0 = fmaxf(z0, 0.f); z1 = fmaxf(z1, 0.f);
    float a = z0 * w2[gi * 64 + j * 2] + z1 * w2[gi * 64 + j * 2 + 1];
    se[t] = 1.f / (1.f + __expf(-a));
}

// ---------------- 6 per-pixel projections (96x96 GEMMs, FFMA2) -----------------
__global__ __launch_bounds__(256, 2)
void k_proj6(const float* __restrict__ l1, const float* __restrict__ h1,
             const float* __restrict__ se,
             const float* __restrict__ Wql, const float* __restrict__ Wkl, const float* __restrict__ Wvl,
             const float* __restrict__ Wqh, const float* __restrict__ Wkh, const float* __restrict__ Wvh,
             float* __restrict__ QL, float* __restrict__ KL, float* __restrict__ VL,
             float* __restrict__ QH, float* __restrict__ KH, float* __restrict__ VH)
{
    extern __shared__ float sm[];
    float* Ws = sm;           // 9216
    float* Xs = sm + 9216;    // 12288
    int row = blockIdx.x;
    int j = blockIdx.y;
    const float* W; const float* X; float* O; bool useSE;
    switch (j) {
        case 0: W = Wql; X = l1; O = QL; useSE = false; break;
        case 1: W = Wkl; X = l1; O = KL; useSE = false; break;
        case 2: W = Wvl; X = l1; O = VL; useSE = false; break;
        case 3: W = Wqh; X = h1; O = QH; useSE = true;  break;
        case 4: W = Wkh; X = h1; O = KH; useSE = true;  break;
        default: W = Wvh; X = h1; O = VH; useSE = true; break;
    }
    int b = row >> 7, h = row & 127;
    int base = b * CB * HW + h * 128;
    int tid = threadIdx.x;

    for (int i = tid; i < 9216; i += 256) Ws[i] = W[i];
    for (int i = tid; i < 12288; i += 256) {
        int c = i >> 7, p = i & 127;
        float v = X[base + c * HW + p];
        if (useSE) v *= se[b * CB + c];
        Xs[i] = v;
    }
    __syncthreads();

    int og = tid >> 4, pg = tid & 15;
    ull acc[6][4];
    #pragma unroll
    for (int r = 0; r < 6; r++)
        #pragma unroll
        for (int i = 0; i < 4; i++) acc[r][i] = 0ull;

    gemm6x8(Ws, Xs, og, pg, acc);

    #pragma unroll
    for (int r = 0; r < 6; r++) {
        int o = og * 6 + r;
        *(ulonglong2*)&O[base + o * HW + pg * 8]     = make_ulonglong2(acc[r][0], acc[r][1]);
        *(ulonglong2*)&O[base + o * HW + pg * 8 + 4] = make_ulonglong2(acc[r][2], acc[r][3]);
    }
}

// ---------------- zero fold accumulators ---------------------------------------
__global__ void k_zero(float4* __restrict__ a, float4* __restrict__ b)
{
    int n = NELEM / 4;
    for (int i = blockIdx.x * blockDim.x + threadIdx.x; i < n;
         i += gridDim.x * blockDim.x) {
        a[i] = make_float4(0.f, 0.f, 0.f, 0.f);
        b[i] = make_float4(0.f, 0.f, 0.f, 0.f);
    }
}

// ---------------- window cross attention (FFMA2, LDS.128 K/V) ------------------
// grid NWINDOWS, 256 thr, dyn smem 73728B
__global__ __launch_bounds__(256, 2)
void k_attn(const float* __restrict__ QL, const float* __restrict__ KL, const float* __restrict__ VL,
            const float* __restrict__ QH, const float* __restrict__ KH, const float* __restrict__ VH,
            float* __restrict__ accL, float* __restrict__ accH, int shift)
{
    extern __shared__ float sm[];
    float* Qs = sm;            // [96][64]            6144
    float* Kt = sm + 6144;     // [4][64][24] m-major 6144
    float* Vt = sm + 12288;    // [4][64][24]         6144

    int win = blockIdx.x;
    int b = win / (NWIN * NWIN);
    int r = win - b * (NWIN * NWIN);
    int wi = r / NWIN, wj = r - wi * NWIN;
    int h0 = wi * 4, w0 = wj * 4;
    int tid = threadIdx.x;

    #pragma unroll 1
    for (int dir = 0; dir < 2; dir++) {
        const float* Qf = dir == 0 ? QL : QH;
        const float* Kf = dir == 0 ? KH : KL;
        const float* Vf = dir == 0 ? VH : VL;
        float* acc = dir == 0 ? accL : accH;

        for (int i = tid; i < 6144; i += 256) {
            int c = i >> 6, p = i & 63;
            int hh = (h0 + (p >> 3) + shift) & 127;
            int ww = (w0 + (p & 7) + shift) & 127;
            int gi = (b * CB + c) * HW + hh * 128 + ww;
            int hd = c / 24, d = c - hd * 24;
            int ti = hd * 1536 + p * 24 + d;
            Qs[i] = Qf[gi];
            Kt[ti] = Kf[gi];
            Vt[ti] = Vf[gi];
        }
        __syncthreads();

        int head = tid >> 6, n = tid & 63;
        const float* Qh = Qs + head * 24 * 64;
        const float* Kb = Kt + head * 1536;
        const float* Vb = Vt + head * 1536;

        ull qp[12];
        #pragma unroll
        for (int jj = 0; jj < 12; jj++)
            qp[jj] = pk2(Qh[(2 * jj) * 64 + n], Qh[(2 * jj + 1) * 64 + n]);

        ull op[12];
        #pragma unroll
        for (int jj = 0; jj < 12; jj++) op[jj] = 0ull;
        float ssum = 0.f;

        for (int m = 0; m < 64; m++) {
            const ulonglong2* Kp = (const ulonglong2*)(Kb + m * 24);
            ull s = 0ull;
            #pragma unroll
            for (int jj = 0; jj < 6; jj++) {
                ulonglong2 kk = Kp[jj];
                ffma2(s, qp[2 * jj],     kk.x);
                ffma2(s, qp[2 * jj + 1], kk.y);
            }
            float slo, shi; upk(s, slo, shi);
            float e = __expf((slo + shi) * ATT_SCALE);
            ssum += e;
            ull ee = pk2(e, e);
            const ulonglong2* Vp = (const ulonglong2*)(Vb + m * 24);
            #pragma unroll
            for (int jj = 0; jj < 6; jj++) {
                ulonglong2 vv = Vp[jj];
                ffma2(op[2 * jj],     ee, vv.x);
                ffma2(op[2 * jj + 1], ee, vv.y);
            }
        }
        float inv = 1.f / ssum;

        int ph = n >> 3, pw = n & 7;
        int base = (b * CB + head * 24) * HW + (h0 + ph) * 128 + (w0 + pw);
        #pragma unroll
        for (int jj = 0; jj < 12; jj++) {
            float lo, hi; upk(op[jj], lo, hi);
            atomicAdd(acc + base + (2 * jj) * HW,     lo * inv);
            atomicAdd(acc + base + (2 * jj + 1) * HW, hi * inv);
        }
        __syncthreads();
    }
}

// ---------------- fold/cnt + output projection + residual (FFMA2) --------------
// dst = src + lnfield + W_proj * (fold(acc)/cnt)
__global__ __launch_bounds__(256, 2)
void k_foldproj(const float* __restrict__ accL, const float* __restrict__ accH,
                const float* __restrict__ wpl, const float* __restrict__ wph,
                const float* __restrict__ srcL, const float* __restrict__ srcH,
                const float* __restrict__ lnL,  const float* __restrict__ lnH,
                float* __restrict__ dstL, float* __restrict__ dstH, int shift)
{
    extern __shared__ float sm[];
    float* Ws  = sm;            // 9216
    float* Xs  = sm + 9216;     // 12288
    float* rcw = sm + 21504;    // 128

    int t = blockIdx.y;
    const float* A   = t ? accH : accL;
    const float* W   = t ? wph  : wpl;
    const float* src = t ? srcH : srcL;
    const float* lnf = t ? lnH  : lnL;
    float*       dst = t ? dstH : dstL;

    int row = blockIdx.x;
    int b = row >> 7, h = row & 127;
    int hr = (h - shift) & 127;
    float invh = 1.f / cnt1f(hr);
    int tid = threadIdx.x;

    if (tid < 128) {
        int wr = (tid - shift) & 127;
        rcw[tid] = invh * (1.f / cnt1f(wr));
    }
    __syncthreads();

    int abase = b * CB * HW + hr * 128;
    for (int i = tid; i < 9216; i += 256) Ws[i] = W[i];
    for (int i = tid; i < 12288; i += 256) {
        int c = i >> 7, p = i & 127;
        int wr = (p - shift) & 127;
        Xs[i] = A[abase + c * HW + wr] * rcw[p];
    }
    __syncthreads();

    int og = tid >> 4, pg = tid & 15;
    ull acc[6][4];
    #pragma unroll
    for (int r = 0; r < 6; r++)
        #pragma unroll
        for (int i = 0; i < 4; i++) acc[r][i] = 0ull;

    gemm6x8(Ws, Xs, og, pg, acc);

    int base = b * CB * HW + h * 128;
    #pragma unroll
    for (int r = 0; r < 6; r++) {
        int o = og * 6 + r;
        int off0 = base + o * HW + pg * 8;
        ulonglong2 s0 = *(const ulonglong2*)&src[off0];
        ulonglong2 s1 = *(const ulonglong2*)&src[off0 + 4];
        ulonglong2 n0 = *(const ulonglong2*)&lnf[off0];
        ulonglong2 n1 = *(const ulonglong2*)&lnf[off0 + 4];
        ulonglong2 o0 = make_ulonglong2(fadd2(fadd2(s0.x, n0.x), acc[r][0]),
                                        fadd2(fadd2(s0.y, n0.y), acc[r][1]));
        ulonglong2 o1 = make_ulonglong2(fadd2(fadd2(s1.x, n1.x), acc[r][2]),
                                        fadd2(fadd2(s1.y, n1.y), acc[r][3]));
        *(ulonglong2*)&dst[off0]     = o0;
        *(ulonglong2*)&dst[off0 + 4] = o1;
    }
}

// ---------------- MLP (96->384 gelu ->96) + residual (FFMA2) -------------------
__global__ __launch_bounds__(256, 1)
void k_mlp(const float* __restrict__ xL, const float* __restrict__ xH,
           const float* __restrict__ w1, const float* __restrict__ b1,
           const float* __restrict__ w2, const float* __restrict__ b2,
           float* __restrict__ outL, float* __restrict__ outH)
{
    extern __shared__ float sm[];
    float* Xs = sm;             // 12288
    float* Hs = sm + 12288;     // 12288
    float* Wc = sm + 24576;     // 9216

    const float* X = blockIdx.y ? xH : xL;
    float*       out = blockIdx.y ? outH : outL;
    int row = blockIdx.x;
    int b = row >> 7, h = row & 127;
    int base = b * CB * HW + h * 128;
    int tid = threadIdx.x;

    for (int i = tid; i < 12288; i += 256) {
        int c = i >> 7, p = i & 127;
        Xs[i] = X[base + c * HW + p];
    }

    int og = tid >> 4, pg = tid & 15;
    ull acc[6][4];
    #pragma unroll
    for (int r = 0; r < 6; r++) {
        float bv = b2[og * 6 + r];
        ull bp = pk2(bv, bv);
        #pragma unroll
        for (int i = 0; i < 4; i++) acc[r][i] = bp;
    }

    for (int k = 0; k < 4; k++) {
        __syncthreads();
        for (int i = tid; i < 9216; i += 256) Wc[i] = w1[k * 9216 + i];
        __syncthreads();

        ull ha[6][4];
        #pragma unroll
        for (int r = 0; r < 6; r++)
            #pragma unroll
            for (int i = 0; i < 4; i++) ha[r][i] = 0ull;

        gemm6x8(Wc, Xs, og, pg, ha);

        #pragma unroll
        for (int r = 0; r < 6; r++) {
            float bb = b1[k * 96 + og * 6 + r];
            float v[8];
            upk(ha[r][0], v[0], v[1]); upk(ha[r][1], v[2], v[3]);
            upk(ha[r][2], v[4], v[5]); upk(ha[r][3], v[6], v[7]);
            float g[8];
            #pragma unroll
            for (int i = 0; i < 8; i++) g[i] = gelu_f(v[i] + bb);
            *(float4*)&Hs[(og * 6 + r) * 128 + pg * 8]     = make_float4(g[0], g[1], g[2], g[3]);
            *(float4*)&Hs[(og * 6 + r) * 128 + pg * 8 + 4] = make_float4(g[4], g[5], g[6], g[7]);
        }
        __syncthreads();
        for (int i = tid; i < 9216; i += 256) {
            int o = i / 96, hl = i - o * 96;
            Wc[i] = w2[o * 384 + k * 96 + hl];
        }
        __syncthreads();

        gemm6x8(Wc, Hs, og, pg, acc);
    }

    #pragma unroll
    for (int r = 0; r < 6; r++) {
        int o = og * 6 + r;
        ulonglong2 xa = *(const ulonglong2*)&Xs[o * 128 + pg * 8];
        ulonglong2 xb = *(const ulonglong2*)&Xs[o * 128 + pg * 8 + 4];
        ulonglong2 o0 = make_ulonglong2(fadd2(xa.x, acc[r][0]), fadd2(xa.y, acc[r][1]));
        ulonglong2 o1 = make_ulonglong2(fadd2(xb.x, acc[r][2]), fadd2(xb.y, acc[r][3]));
        *(ulonglong2*)&out[base + o * HW + pg * 8]     = o0;
        *(ulonglong2*)&out[base + o * HW + pg * 8 + 4] = o1;
    }
}

// ---------------- host orchestration -------------------------------------------
static float* symaddr(const void* sym)
{
    void* p = nullptr;
    cudaGetSymbolAddress(&p, sym);
    return (float*)p;
}

extern "C" void kernel_launch(void* const* d_in, const int* in_sizes, int n_in,
                              void* d_out, int out_size)
{
    const float* low    = (const float*)d_in[0];
    const float* high   = (const float*)d_in[1];
    const float* ln1g   = (const float*)d_in[2];
    const float* ln1b   = (const float*)d_in[3];
    const float* ln2g   = (const float*)d_in[4];
    const float* ln2b   = (const float*)d_in[5];
    const float* se_w1  = (const float*)d_in[6];
    const float* se_w2  = (const float*)d_in[7];
    const float* wq_l   = (const float*)d_in[8];
    const float* wk_h   = (const float*)d_in[9];
    const float* wv_h   = (const float*)d_in[10];
    const float* wq_h   = (const float*)d_in[11];
    const float* wk_l   = (const float*)d_in[12];
    const float* wv_l   = (const float*)d_in[13];
    const float* wp_l   = (const float*)d_in[14];
    const float* wp_h   = (const float*)d_in[15];
    const float* mlp_w1 = (const float*)d_in[16];
    const float* mlp_b1 = (const float*)d_in[17];
    const float* mlp_w2 = (const float*)d_in[18];
    const float* mlp_b2 = (const float*)d_in[19];
    float* out = (float*)d_out;

    float* l1   = symaddr(g_l1);    float* h1   = symaddr(g_h1);
    float* QL   = symaddr(g_QL);    float* KL   = symaddr(g_KL);  float* VL = symaddr(g_VL);
    float* QH   = symaddr(g_QH);    float* KH   = symaddr(g_KH);  float* VH = symaddr(g_VH);
    float* accL = symaddr(g_accL);  float* accH = symaddr(g_accH);
    float* low1 = symaddr(g_low1);  float* high1 = symaddr(g_high1);
    float* low2 = symaddr(g_low2);  float* high2 = symaddr(g_high2);
    float* pool = symaddr(g_pool);  float* se    = symaddr(g_se);

    cudaFuncSetAttribute(k_ln,       cudaFuncAttributeMaxDynamicSharedMemorySize, 50176);
    cudaFuncSetAttribute(k_proj6,    cudaFuncAttributeMaxDynamicSharedMemorySize, 86016);
    cudaFuncSetAttribute(k_attn,     cudaFuncAttributeMaxDynamicSharedMemorySize, 73728);
    cudaFuncSetAttribute(k_foldproj, cudaFuncAttributeMaxDynamicSharedMemorySize, 86528);
    cudaFuncSetAttribute(k_mlp,      cudaFuncAttributeMaxDynamicSharedMemorySize, 135168);

    dim3 gRow2(NB * HWIMG, 2);
    dim3 gProj(NB * HWIMG, 6);

    // ---------------- pass 1 (shift = 0, ln1) ----------------
    k_ln<<<gRow2, 256, 50176>>>(low, high, ln1g, ln1b, l1, h1);
    k_pool<<<NB * CB, 256>>>(h1, pool);
    k_se<<<1, 256>>>(pool, se_w1, se_w2, se);
    k_proj6<<<gProj, 256, 86016>>>(l1, h1, se, wq_l, wk_l, wv_l, wq_h, wk_h, wv_h,
                                   QL, KL, VL, QH, KH, VH);
    k_zero<<<1024, 256>>>((float4*)accL, (float4*)accH);
    k_attn<<<NWINDOWS, 256, 73728>>>(QL, KL, VL, QH, KH, VH, accL, accH, 0);
    k_foldproj<<<gRow2, 256, 86528>>>(accL, accH, wp_l, wp_h, low, high, l1, h1,
                                      low1, high1, 0);

    // ---------------- pass 2 (shift = 4, ln2) ----------------
    k_ln<<<gRow2, 256, 50176>>>(low1, high1, ln2g, ln2b, l1, h1);
    k_pool<<<NB * CB, 256>>>(h1, pool);
    k_se<<<1, 256>>>(pool, se_w1, se_w2, se);
    k_proj6<<<gProj, 256, 86016>>>(l1, h1, se, wq_l, wk_l, wv_l, wq_h, wk_h, wv_h,
                                   QL, KL, VL, QH, KH, VH);
    k_zero<<<1024, 256>>>((float4*)accL, (float4*)accH);
    k_attn<<<NWINDOWS, 256, 73728>>>(QL, KL, VL, QH, KH, VH, accL, accH, 4);
    k_foldproj<<<gRow2, 256, 86528>>>(accL, accH, wp_l, wp_h, low1, high1, l1, h1,
                                      low2, high2, 4);

    // ---------------- MLP + residual -> output ----------------
    k_mlp<<<gRow2, 256, 135168>>>(low2, high2, mlp_w1, mlp_b1, mlp_w2, mlp_b2,
                                  out, out + NELEM);
}

// round 9
// speedup vs baseline: 1.2541x; 1.0347x over previous
#include <cuda_runtime.h>
#include <math.h>

#define CB     96
#define HWIMG  128
#define HW     16384          // 128*128
#define NB     2
#define NELEM  3145728        // NB*CB*HW
#define NWIN   31
#define NWINDOWS 1922         // NB*31*31
#define ATT_SCALE 0.20412414523193154f  // 1/sqrt(24)

typedef unsigned long long ull;

// ---------------- packed f32x2 helpers (sm_103a FFMA2) --------------------------
__device__ __forceinline__ ull pk2(float lo, float hi) {
    ull r; asm("mov.b64 %0,{%1,%2};" : "=l"(r) : "f"(lo), "f"(hi)); return r;
}
__device__ __forceinline__ void upk(ull v, float& lo, float& hi) {
    asm("mov.b64 {%0,%1},%2;" : "=f"(lo), "=f"(hi) : "l"(v));
}
__device__ __forceinline__ void ffma2(ull& d, ull a, ull b) {
    asm("fma.rn.f32x2 %0,%1,%2,%0;" : "+l"(d) : "l"(a), "l"(b));
}
__device__ __forceinline__ ull fadd2(ull a, ull b) {
    ull r; asm("add.rn.f32x2 %0,%1,%2;" : "=l"(r) : "l"(a), "l"(b)); return r;
}

// ---------------- scratch (static device globals; alloc-free rule) -------------
__device__ float g_l1[NELEM], g_h1[NELEM];
__device__ float g_QL[NELEM], g_KL[NELEM], g_VL[NELEM];
__device__ float g_QH[NELEM], g_KH[NELEM], g_VH[NELEM];
__device__ float g_accL[NELEM], g_accH[NELEM];
__device__ float g_low1[NELEM], g_high1[NELEM];
__device__ float g_low2[NELEM], g_high2[NELEM];
__device__ float g_pool[NB*CB], g_se[NB*CB];

// ---------------- helpers ------------------------------------------------------
__device__ __forceinline__ float cnt1f(int h) {
    int imin = (h <= 7) ? 0 : ((h - 4) >> 2);
    int imax = min(30, h >> 2);
    return (float)(imax - imin + 1);
}

__device__ __forceinline__ float gelu_f(float v) {
    float u = 0.7978845608028654f * (v + 0.044715f * v * v * v);
    float t = 1.f - 2.f / (__expf(2.f * u) + 1.f);
    return 0.5f * v * (1.f + t);
}

// 6-row x 8-px FFMA2 micro-tile; weights read straight from GLOBAL (L1-resident,
// broadcast LDG.128 across lanes), X from smem [96][128]. All loads of a chunk
// are issued before the FMA burst so LDS/LDG latency pipelines.
__device__ __forceinline__ void gemm6x8g(const float* __restrict__ Wg, int wstride,
                                         const float* __restrict__ Xs,
                                         int og, int pg, ull acc[6][4])
{
    #pragma unroll 1
    for (int c4 = 0; c4 < CB; c4 += 4) {
        float4 wv[6];
        #pragma unroll
        for (int r = 0; r < 6; r++)
            wv[r] = *(const float4*)&Wg[(og * 6 + r) * wstride + c4];
        ulonglong2 xv[8];
        #pragma unroll
        for (int cc = 0; cc < 4; cc++) {
            const float* xp = &Xs[(c4 + cc) * 128 + pg * 8];
            xv[2 * cc]     = *(const ulonglong2*)xp;
            xv[2 * cc + 1] = *(const ulonglong2*)(xp + 4);
        }
        #pragma unroll
        for (int cc = 0; cc < 4; cc++) {
            #pragma unroll
            for (int r = 0; r < 6; r++) {
                float w = cc == 0 ? wv[r].x : cc == 1 ? wv[r].y
                        : cc == 2 ? wv[r].z : wv[r].w;
                ull ww = pk2(w, w);
                ffma2(acc[r][0], ww, xv[2 * cc].x);
                ffma2(acc[r][1], ww, xv[2 * cc].y);
                ffma2(acc[r][2], ww, xv[2 * cc + 1].x);
                ffma2(acc[r][3], ww, xv[2 * cc + 1].y);
            }
        }
    }
}

// ---------------- LN over channel axis, per pixel ------------------------------
__global__ void k_ln(const float* __restrict__ srcL, const float* __restrict__ srcH,
                     const float* __restrict__ gw,  const float* __restrict__ bw,
                     float* __restrict__ dstL, float* __restrict__ dstH)
{
    extern __shared__ float sm[];
    float* Xs = sm;              // 96*128
    float* mu = sm + 12288;
    float* rv = sm + 12416;
    const float* src = blockIdx.y ? srcH : srcL;
    float*       dst = blockIdx.y ? dstH : dstL;
    int row = blockIdx.x;
    int b = row >> 7, h = row & 127;
    int base = b * CB * HW + h * 128;
    int tid = threadIdx.x;

    for (int i = tid; i < 12288; i += 256) {
        int c = i >> 7, p = i & 127;
        Xs[i] = src[base + c * HW + p];
    }
    __syncthreads();
    if (tid < 128) {
        float s = 0.f, s2 = 0.f;
        #pragma unroll 8
        for (int c = 0; c < CB; c++) {
            float v = Xs[c * 128 + tid];
            s += v; s2 += v * v;
        }
        float m = s * (1.f / 96.f);
        float var = s2 * (1.f / 96.f) - m * m;
        mu[tid] = m;
        rv[tid] = rsqrtf(var + 1e-5f);
    }
    __syncthreads();
    for (int i = tid; i < 12288; i += 256) {
        int c = i >> 7, p = i & 127;
        dst[base + c * HW + p] = (Xs[i] - mu[p]) * rv[p] * gw[c] + bw[c];
    }
}

// ---------------- SE: spatial mean pool per (b,c) ------------------------------
__global__ void k_pool(const float* __restrict__ h1, float* __restrict__ pool)
{
    int bc = blockIdx.x;
    const float* p = h1 + bc * HW;
    float s = 0.f;
    for (int i = threadIdx.x; i < HW; i += 256) s += p[i];
    __shared__ float red[256];
    red[threadIdx.x] = s; __syncthreads();
    for (int o = 128; o > 0; o >>= 1) {
        if (threadIdx.x < o) red[threadIdx.x] += red[threadIdx.x + o];
        __syncthreads();
    }
    if (threadIdx.x == 0) pool[bc] = red[0] * (1.f / 16384.f);
}

// ---------------- SE: FC -> relu -> FC -> sigmoid ------------------------------
__global__ void k_se(const float* __restrict__ pool, const float* __restrict__ w1,
                     const float* __restrict__ w2, float* __restrict__ se)
{
    int t = threadIdx.x;
    if (t >= NB * CB) return;
    int b = t / CB, c = t % CB;
    int gi = c >> 5, j = c & 31;
    const float* pl = pool + b * CB + gi * 32;
    float z0 = 0.f, z1 = 0.f;
    #pragma unroll
    for (int g = 0; g < 32; g++) {
        float pv = pl[g];
        z0 += pv * w1[gi * 64 + g];
        z1 += pv * w1[gi * 64 + 32 + g];
    }
    z0 = fmaxf(z0, 0.f); z1 = fmaxf(z1, 0.f);
    float a = z0 * w2[gi * 64 + j * 2] + z1 * w2[gi * 64 + j * 2 + 1];
    se[t] = 1.f / (1.f + __expf(-a));
}

// ---------------- 6 per-pixel projections (96x96 GEMMs, FFMA2) -----------------
// smem: Xs only (49152B)
__global__ __launch_bounds__(256, 2)
void k_proj6(const float* __restrict__ l1, const float* __restrict__ h1,
             const float* __restrict__ se,
             const float* __restrict__ Wql, const float* __restrict__ Wkl, const float* __restrict__ Wvl,
             const float* __restrict__ Wqh, const float* __restrict__ Wkh, const float* __restrict__ Wvh,
             float* __restrict__ QL, float* __restrict__ KL, float* __restrict__ VL,
             float* __restrict__ QH, float* __restrict__ KH, float* __restrict__ VH)
{
    extern __shared__ float sm[];
    float* Xs = sm;           // 12288
    int row = blockIdx.x;
    int j = blockIdx.y;
    const float* W; const float* X; float* O; bool useSE;
    switch (j) {
        case 0: W = Wql; X = l1; O = QL; useSE = false; break;
        case 1: W = Wkl; X = l1; O = KL; useSE = false; break;
        case 2: W = Wvl; X = l1; O = VL; useSE = false; break;
        case 3: W = Wqh; X = h1; O = QH; useSE = true;  break;
        case 4: W = Wkh; X = h1; O = KH; useSE = true;  break;
        default: W = Wvh; X = h1; O = VH; useSE = true; break;
    }
    int b = row >> 7, h = row & 127;
    int base = b * CB * HW + h * 128;
    int tid = threadIdx.x;

    for (int i = tid; i < 12288; i += 256) {
        int c = i >> 7, p = i & 127;
        float v = X[base + c * HW + p];
        if (useSE) v *= se[b * CB + c];
        Xs[i] = v;
    }
    __syncthreads();

    int og = tid >> 4, pg = tid & 15;
    ull acc[6][4];
    #pragma unroll
    for (int r = 0; r < 6; r++)
        #pragma unroll
        for (int i = 0; i < 4; i++) acc[r][i] = 0ull;

    gemm6x8g(W, 96, Xs, og, pg, acc);

    #pragma unroll
    for (int r = 0; r < 6; r++) {
        int o = og * 6 + r;
        *(ulonglong2*)&O[base + o * HW + pg * 8]     = make_ulonglong2(acc[r][0], acc[r][1]);
        *(ulonglong2*)&O[base + o * HW + pg * 8 + 4] = make_ulonglong2(acc[r][2], acc[r][3]);
    }
}

// ---------------- zero fold accumulators ---------------------------------------
__global__ void k_zero(float4* __restrict__ a, float4* __restrict__ b)
{
    int n = NELEM / 4;
    for (int i = blockIdx.x * blockDim.x + threadIdx.x; i < n;
         i += gridDim.x * blockDim.x) {
        a[i] = make_float4(0.f, 0.f, 0.f, 0.f);
        b[i] = make_float4(0.f, 0.f, 0.f, 0.f);
    }
}

// ---------------- window cross attention (FFMA2, LDS.128 K/V) ------------------
// grid NWINDOWS, 256 thr, dyn smem 73728B
__global__ __launch_bounds__(256, 2)
void k_attn(const float* __restrict__ QL, const float* __restrict__ KL, const float* __restrict__ VL,
            const float* __restrict__ QH, const float* __restrict__ KH, const float* __restrict__ VH,
            float* __restrict__ accL, float* __restrict__ accH, int shift)
{
    extern __shared__ float sm[];
    float* Qs = sm;            // [96][64]            6144
    float* Kt = sm + 6144;     // [4][64][24] m-major 6144
    float* Vt = sm + 12288;    // [4][64][24]         6144

    int win = blockIdx.x;
    int b = win / (NWIN * NWIN);
    int r = win - b * (NWIN * NWIN);
    int wi = r / NWIN, wj = r - wi * NWIN;
    int h0 = wi * 4, w0 = wj * 4;
    int tid = threadIdx.x;

    #pragma unroll 1
    for (int dir = 0; dir < 2; dir++) {
        const float* Qf = dir == 0 ? QL : QH;
        const float* Kf = dir == 0 ? KH : KL;
        const float* Vf = dir == 0 ? VH : VL;
        float* acc = dir == 0 ? accL : accH;

        for (int i = tid; i < 6144; i += 256) {
            int c = i >> 6, p = i & 63;
            int hh = (h0 + (p >> 3) + shift) & 127;
            int ww = (w0 + (p & 7) + shift) & 127;
            int gi = (b * CB + c) * HW + hh * 128 + ww;
            int hd = c / 24, d = c - hd * 24;
            int ti = hd * 1536 + p * 24 + d;
            Qs[i] = Qf[gi];
            Kt[ti] = Kf[gi];
            Vt[ti] = Vf[gi];
        }
        __syncthreads();

        int head = tid >> 6, n = tid & 63;
        const float* Qh = Qs + head * 24 * 64;
        const float* Kb = Kt + head * 1536;
        const float* Vb = Vt + head * 1536;

        ull qp[12];
        #pragma unroll
        for (int jj = 0; jj < 12; jj++)
            qp[jj] = pk2(Qh[(2 * jj) * 64 + n], Qh[(2 * jj + 1) * 64 + n]);

        ull op[12];
        #pragma unroll
        for (int jj = 0; jj < 12; jj++) op[jj] = 0ull;
        float ssum = 0.f;

        #pragma unroll 2
        for (int m = 0; m < 64; m++) {
            const ulonglong2* Kp = (const ulonglong2*)(Kb + m * 24);
            ull s = 0ull;
            #pragma unroll
            for (int jj = 0; jj < 6; jj++) {
                ulonglong2 kk = Kp[jj];
                ffma2(s, qp[2 * jj],     kk.x);
                ffma2(s, qp[2 * jj + 1], kk.y);
            }
            float slo, shi; upk(s, slo, shi);
            float e = __expf((slo + shi) * ATT_SCALE);
            ssum += e;
            ull ee = pk2(e, e);
            const ulonglong2* Vp = (const ulonglong2*)(Vb + m * 24);
            #pragma unroll
            for (int jj = 0; jj < 6; jj++) {
                ulonglong2 vv = Vp[jj];
                ffma2(op[2 * jj],     ee, vv.x);
                ffma2(op[2 * jj + 1], ee, vv.y);
            }
        }
        float inv = 1.f / ssum;

        int ph = n >> 3, pw = n & 7;
        int base = (b * CB + head * 24) * HW + (h0 + ph) * 128 + (w0 + pw);
        #pragma unroll
        for (int jj = 0; jj < 12; jj++) {
            float lo, hi; upk(op[jj], lo, hi);
            atomicAdd(acc + base + (2 * jj) * HW,     lo * inv);
            atomicAdd(acc + base + (2 * jj + 1) * HW, hi * inv);
        }
        __syncthreads();
    }
}

// ---------------- fold/cnt + output projection + residual (FFMA2) --------------
// dst = src + lnfield + W_proj * (fold(acc)/cnt)   smem 49664B
__global__ __launch_bounds__(256, 2)
void k_foldproj(const float* __restrict__ accL, const float* __restrict__ accH,
                const float* __restrict__ wpl, const float* __restrict__ wph,
                const float* __restrict__ srcL, const float* __restrict__ srcH,
                const float* __restrict__ lnL,  const float* __restrict__ lnH,
                float* __restrict__ dstL, float* __restrict__ dstH, int shift)
{
    extern __shared__ float sm[];
    float* Xs  = sm;            // 12288
    float* rcw = sm + 12288;    // 128

    int t = blockIdx.y;
    const float* A   = t ? accH : accL;
    const float* W   = t ? wph  : wpl;
    const float* src = t ? srcH : srcL;
    const float* lnf = t ? lnH  : lnL;
    float*       dst = t ? dstH : dstL;

    int row = blockIdx.x;
    int b = row >> 7, h = row & 127;
    int hr = (h - shift) & 127;
    float invh = 1.f / cnt1f(hr);
    int tid = threadIdx.x;

    if (tid < 128) {
        int wr = (tid - shift) & 127;
        rcw[tid] = invh * (1.f / cnt1f(wr));
    }
    __syncthreads();

    int abase = b * CB * HW + hr * 128;
    for (int i = tid; i < 12288; i += 256) {
        int c = i >> 7, p = i & 127;
        int wr = (p - shift) & 127;
        Xs[i] = A[abase + c * HW + wr] * rcw[p];
    }
    __syncthreads();

    int og = tid >> 4, pg = tid & 15;
    ull acc[6][4];
    #pragma unroll
    for (int r = 0; r < 6; r++)
        #pragma unroll
        for (int i = 0; i < 4; i++) acc[r][i] = 0ull;

    gemm6x8g(W, 96, Xs, og, pg, acc);

    int base = b * CB * HW + h * 128;
    #pragma unroll
    for (int r = 0; r < 6; r++) {
        int o = og * 6 + r;
        int off0 = base + o * HW + pg * 8;
        ulonglong2 s0 = *(const ulonglong2*)&src[off0];
        ulonglong2 s1 = *(const ulonglong2*)&src[off0 + 4];
        ulonglong2 n0 = *(const ulonglong2*)&lnf[off0];
        ulonglong2 n1 = *(const ulonglong2*)&lnf[off0 + 4];
        ulonglong2 o0 = make_ulonglong2(fadd2(fadd2(s0.x, n0.x), acc[r][0]),
                                        fadd2(fadd2(s0.y, n0.y), acc[r][1]));
        ulonglong2 o1 = make_ulonglong2(fadd2(fadd2(s1.x, n1.x), acc[r][2]),
                                        fadd2(fadd2(s1.y, n1.y), acc[r][3]));
        *(ulonglong2*)&dst[off0]     = o0;
        *(ulonglong2*)&dst[off0 + 4] = o1;
    }
}

// ---------------- MLP (96->384 gelu ->96) + residual (FFMA2) -------------------
// weights from global (L1); smem = Xs + Hs = 98304B -> 2 CTAs/SM
__global__ __launch_bounds__(256, 2)
void k_mlp(const float* __restrict__ xL, const float* __restrict__ xH,
           const float* __restrict__ w1, const float* __restrict__ b1,
           const float* __restrict__ w2, const float* __restrict__ b2,
           float* __restrict__ outL, float* __restrict__ outH)
{
    extern __shared__ float sm[];
    float* Xs = sm;             // 12288
    float* Hs = sm + 12288;     // 12288

    const float* X = blockIdx.y ? xH : xL;
    float*       out = blockIdx.y ? outH : outL;
    int row = blockIdx.x;
    int b = row >> 7, h = row & 127;
    int base = b * CB * HW + h * 128;
    int tid = threadIdx.x;

    for (int i = tid; i < 12288; i += 256) {
        int c = i >> 7, p = i & 127;
        Xs[i] = X[base + c * HW + p];
    }
    __syncthreads();

    int og = tid >> 4, pg = tid & 15;
    ull acc[6][4];
    #pragma unroll
    for (int r = 0; r < 6; r++) {
        float bv = b2[og * 6 + r];
        ull bp = pk2(bv, bv);
        #pragma unroll
        for (int i = 0; i < 4; i++) acc[r][i] = bp;
    }

    #pragma unroll 1
    for (int k = 0; k < 4; k++) {
        ull ha[6][4];
        #pragma unroll
        for (int r = 0; r < 6; r++)
            #pragma unroll
            for (int i = 0; i < 4; i++) ha[r][i] = 0ull;

        // h-chunk rows k*96 + og*6 + r of w1 (stride 96)
        gemm6x8g(w1 + k * 96 * 96, 96, Xs, og, pg, ha);

        #pragma unroll
        for (int r = 0; r < 6; r++) {
            float bb = b1[k * 96 + og * 6 + r];
            float v[8];
            upk(ha[r][0], v[0], v[1]); upk(ha[r][1], v[2], v[3]);
            upk(ha[r][2], v[4], v[5]); upk(ha[r][3], v[6], v[7]);
            float g[8];
            #pragma unroll
            for (int i = 0; i < 8; i++) g[i] = gelu_f(v[i] + bb);
            *(float4*)&Hs[(og * 6 + r) * 128 + pg * 8]     = make_float4(g[0], g[1], g[2], g[3]);
            *(float4*)&Hs[(og * 6 + r) * 128 + pg * 8 + 4] = make_float4(g[4], g[5], g[6], g[7]);
        }
        __syncthreads();

        // out rows og*6+r of w2 (stride 384), k-th 96-chunk
        gemm6x8g(w2 + k * 96, 384, Hs, og, pg, acc);
        __syncthreads();
    }

    #pragma unroll
    for (int r = 0; r < 6; r++) {
        int o = og * 6 + r;
        ulonglong2 xa = *(const ulonglong2*)&Xs[o * 128 + pg * 8];
        ulonglong2 xb = *(const ulonglong2*)&Xs[o * 128 + pg * 8 + 4];
        ulonglong2 o0 = make_ulonglong2(fadd2(xa.x, acc[r][0]), fadd2(xa.y, acc[r][1]));
        ulonglong2 o1 = make_ulonglong2(fadd2(xb.x, acc[r][2]), fadd2(xb.y, acc[r][3]));
        *(ulonglong2*)&out[base + o * HW + pg * 8]     = o0;
        *(ulonglong2*)&out[base + o * HW + pg * 8 + 4] = o1;
    }
}

// ---------------- host orchestration -------------------------------------------
static float* symaddr(const void* sym)
{
    void* p = nullptr;
    cudaGetSymbolAddress(&p, sym);
    return (float*)p;
}

extern "C" void kernel_launch(void* const* d_in, const int* in_sizes, int n_in,
                              void* d_out, int out_size)
{
    const float* low    = (const float*)d_in[0];
    const float* high   = (const float*)d_in[1];
    const float* ln1g   = (const float*)d_in[2];
    const float* ln1b   = (const float*)d_in[3];
    const float* ln2g   = (const float*)d_in[4];
    const float* ln2b   = (const float*)d_in[5];
    const float* se_w1  = (const float*)d_in[6];
    const float* se_w2  = (const float*)d_in[7];
    const float* wq_l   = (const float*)d_in[8];
    const float* wk_h   = (const float*)d_in[9];
    const float* wv_h   = (const float*)d_in[10];
    const float* wq_h   = (const float*)d_in[11];
    const float* wk_l   = (const float*)d_in[12];
    const float* wv_l   = (const float*)d_in[13];
    const float* wp_l   = (const float*)d_in[14];
    const float* wp_h   = (const float*)d_in[15];
    const float* mlp_w1 = (const float*)d_in[16];
    const float* mlp_b1 = (const float*)d_in[17];
    const float* mlp_w2 = (const float*)d_in[18];
    const float* mlp_b2 = (const float*)d_in[19];
    float* out = (float*)d_out;

    float* l1   = symaddr(g_l1);    float* h1   = symaddr(g_h1);
    float* QL   = symaddr(g_QL);    float* KL   = symaddr(g_KL);  float* VL = symaddr(g_VL);
    float* QH   = symaddr(g_QH);    float* KH   = symaddr(g_KH);  float* VH = symaddr(g_VH);
    float* accL = symaddr(g_accL);  float* accH = symaddr(g_accH);
    float* low1 = symaddr(g_low1);  float* high1 = symaddr(g_high1);
    float* low2 = symaddr(g_low2);  float* high2 = symaddr(g_high2);
    float* pool = symaddr(g_pool);  float* se    = symaddr(g_se);

    cudaFuncSetAttribute(k_ln,       cudaFuncAttributeMaxDynamicSharedMemorySize, 50176);
    cudaFuncSetAttribute(k_proj6,    cudaFuncAttributeMaxDynamicSharedMemorySize, 49152);
    cudaFuncSetAttribute(k_attn,     cudaFuncAttributeMaxDynamicSharedMemorySize, 73728);
    cudaFuncSetAttribute(k_foldproj, cudaFuncAttributeMaxDynamicSharedMemorySize, 49664);
    cudaFuncSetAttribute(k_mlp,      cudaFuncAttributeMaxDynamicSharedMemorySize, 98304);

    dim3 gRow2(NB * HWIMG, 2);
    dim3 gProj(NB * HWIMG, 6);

    // ---------------- pass 1 (shift = 0, ln1) ----------------
    k_ln<<<gRow2, 256, 50176>>>(low, high, ln1g, ln1b, l1, h1);
    k_pool<<<NB * CB, 256>>>(h1, pool);
    k_se<<<1, 256>>>(pool, se_w1, se_w2, se);
    k_proj6<<<gProj, 256, 49152>>>(l1, h1, se, wq_l, wk_l, wv_l, wq_h, wk_h, wv_h,
                                   QL, KL, VL, QH, KH, VH);
    k_zero<<<1024, 256>>>((float4*)accL, (float4*)accH);
    k_attn<<<NWINDOWS, 256, 73728>>>(QL, KL, VL, QH, KH, VH, accL, accH, 0);
    k_foldproj<<<gRow2, 256, 49664>>>(accL, accH, wp_l, wp_h, low, high, l1, h1,
                                      low1, high1, 0);

    // ---------------- pass 2 (shift = 4, ln2) ----------------
    k_ln<<<gRow2, 256, 50176>>>(low1, high1, ln2g, ln2b, l1, h1);
    k_pool<<<NB * CB, 256>>>(h1, pool);
    k_se<<<1, 256>>>(pool, se_w1, se_w2, se);
    k_proj6<<<gProj, 256, 49152>>>(l1, h1, se, wq_l, wk_l, wv_l, wq_h, wk_h, wv_h,
                                   QL, KL, VL, QH, KH, VH);
    k_zero<<<1024, 256>>>((float4*)accL, (float4*)accH);
    k_attn<<<NWINDOWS, 256, 73728>>>(QL, KL, VL, QH, KH, VH, accL, accH, 4);
    k_foldproj<<<gRow2, 256, 49664>>>(accL, accH, wp_l, wp_h, low1, high1, l1, h1,
                                      low2, high2, 4);

    // ---------------- MLP + residual -> output ----------------
    k_mlp<<<gRow2, 256, 98304>>>(low2, high2, mlp_w1, mlp_b1, mlp_w2, mlp_b2,
                                 out, out + NELEM);
}

// round 11
// speedup vs baseline: 1.3529x; 1.0788x over previous
#include <cuda_runtime.h>
#include <math.h>

#define CB     96
#define HWIMG  128
#define HW     16384          // 128*128
#define NB     2
#define NELEM  3145728        // NB*CB*HW
#define NWIN   31
#define NWINDOWS 1922         // NB*31*31
#define ATT_SCALE 0.20412414523193154f  // 1/sqrt(24)

typedef unsigned long long ull;

// ---------------- packed f32x2 helpers (sm_103a FFMA2) --------------------------
__device__ __forceinline__ ull pk2(float lo, float hi) {
    ull r; asm("mov.b64 %0,{%1,%2};" : "=l"(r) : "f"(lo), "f"(hi)); return r;
}
__device__ __forceinline__ void upk(ull v, float& lo, float& hi) {
    asm("mov.b64 {%0,%1},%2;" : "=f"(lo), "=f"(hi) : "l"(v));
}
__device__ __forceinline__ void ffma2(ull& d, ull a, ull b) {
    asm("fma.rn.f32x2 %0,%1,%2,%0;" : "+l"(d) : "l"(a), "l"(b));
}
__device__ __forceinline__ ull fadd2(ull a, ull b) {
    ull r; asm("add.rn.f32x2 %0,%1,%2;" : "=l"(r) : "l"(a), "l"(b)); return r;
}

// ---------------- scratch (static device globals; alloc-free rule) -------------
__device__ float g_l1[NELEM], g_h1[NELEM];
__device__ float g_QL[NELEM], g_KL[NELEM], g_VL[NELEM];
__device__ float g_QH[NELEM], g_KH[NELEM], g_VH[NELEM];
__device__ float g_accL[NELEM], g_accH[NELEM];
__device__ float g_low1[NELEM], g_high1[NELEM];
__device__ float g_low2[NELEM], g_high2[NELEM];
__device__ float g_pool[NB*CB], g_se[NB*CB];

// ---------------- helpers ------------------------------------------------------
__device__ __forceinline__ float cnt1f(int h) {
    int imin = (h <= 7) ? 0 : ((h - 4) >> 2);
    int imax = min(30, h >> 2);
    return (float)(imax - imin + 1);
}

__device__ __forceinline__ float gelu_f(float v) {
    float u = 0.7978845608028654f * (v + 0.044715f * v * v * v);
    float t = 1.f - 2.f / (__expf(2.f * u) + 1.f);
    return 0.5f * v * (1.f + t);
}

// ---------------- 12-row x 8-px FFMA2 micro-tile (128-thread blocks) -----------
// Weights from global (L1-resident broadcast), X from smem [96][128].
// Weight rows processed 6 at a time to bound live registers.
__device__ __forceinline__ void gemm12x8g(const float* __restrict__ Wg, int wstride,
                                          const float* __restrict__ Xs,
                                          int og, int pg, ull acc[12][4])
{
    #pragma unroll 1
    for (int c4 = 0; c4 < CB; c4 += 4) {
        ulonglong2 xv[8];
        #pragma unroll
        for (int cc = 0; cc < 4; cc++) {
            const float* xp = &Xs[(c4 + cc) * 128 + pg * 8];
            xv[2 * cc]     = *(const ulonglong2*)xp;
            xv[2 * cc + 1] = *(const ulonglong2*)(xp + 4);
        }
        #pragma unroll
        for (int half = 0; half < 2; half++) {
            float4 wv[6];
            #pragma unroll
            for (int r = 0; r < 6; r++)
                wv[r] = *(const float4*)&Wg[(og * 12 + half * 6 + r) * wstride + c4];
            #pragma unroll
            for (int cc = 0; cc < 4; cc++) {
                #pragma unroll
                for (int r = 0; r < 6; r++) {
                    float w = cc == 0 ? wv[r].x : cc == 1 ? wv[r].y
                            : cc == 2 ? wv[r].z : wv[r].w;
                    ull ww = pk2(w, w);
                    int ar = half * 6 + r;
                    ffma2(acc[ar][0], ww, xv[2 * cc].x);
                    ffma2(acc[ar][1], ww, xv[2 * cc].y);
                    ffma2(acc[ar][2], ww, xv[2 * cc + 1].x);
                    ffma2(acc[ar][3], ww, xv[2 * cc + 1].y);
                }
            }
        }
    }
}

// 6-row x 8-px variant (256-thread blocks) — used by k_mlp.
__device__ __forceinline__ void gemm6x8g(const float* __restrict__ Wg, int wstride,
                                         const float* __restrict__ Xs,
                                         int og, int pg, ull acc[6][4])
{
    #pragma unroll 1
    for (int c4 = 0; c4 < CB; c4 += 4) {
        float4 wv[6];
        #pragma unroll
        for (int r = 0; r < 6; r++)
            wv[r] = *(const float4*)&Wg[(og * 6 + r) * wstride + c4];
        ulonglong2 xv[8];
        #pragma unroll
        for (int cc = 0; cc < 4; cc++) {
            const float* xp = &Xs[(c4 + cc) * 128 + pg * 8];
            xv[2 * cc]     = *(const ulonglong2*)xp;
            xv[2 * cc + 1] = *(const ulonglong2*)(xp + 4);
        }
        #pragma unroll
        for (int cc = 0; cc < 4; cc++) {
            #pragma unroll
            for (int r = 0; r < 6; r++) {
                float w = cc == 0 ? wv[r].x : cc == 1 ? wv[r].y
                        : cc == 2 ? wv[r].z : wv[r].w;
                ull ww = pk2(w, w);
                ffma2(acc[r][0], ww, xv[2 * cc].x);
                ffma2(acc[r][1], ww, xv[2 * cc].y);
                ffma2(acc[r][2], ww, xv[2 * cc + 1].x);
                ffma2(acc[r][3], ww, xv[2 * cc + 1].y);
            }
        }
    }
}

// ---------------- LN over channel axis, per pixel ------------------------------
__global__ void k_ln(const float* __restrict__ srcL, const float* __restrict__ srcH,
                     const float* __restrict__ gw,  const float* __restrict__ bw,
                     float* __restrict__ dstL, float* __restrict__ dstH)
{
    extern __shared__ float sm[];
    float* Xs = sm;              // 96*128
    float* mu = sm + 12288;
    float* rv = sm + 12416;
    const float* src = blockIdx.y ? srcH : srcL;
    float*       dst = blockIdx.y ? dstH : dstL;
    int row = blockIdx.x;
    int b = row >> 7, h = row & 127;
    int base = b * CB * HW + h * 128;
    int tid = threadIdx.x;

    for (int i = tid; i < 12288; i += 256) {
        int c = i >> 7, p = i & 127;
        Xs[i] = src[base + c * HW + p];
    }
    __syncthreads();
    if (tid < 128) {
        float s = 0.f, s2 = 0.f;
        #pragma unroll 8
        for (int c = 0; c < CB; c++) {
            float v = Xs[c * 128 + tid];
            s += v; s2 += v * v;
        }
        float m = s * (1.f / 96.f);
        float var = s2 * (1.f / 96.f) - m * m;
        mu[tid] = m;
        rv[tid] = rsqrtf(var + 1e-5f);
    }
    __syncthreads();
    for (int i = tid; i < 12288; i += 256) {
        int c = i >> 7, p = i & 127;
        dst[base + c * HW + p] = (Xs[i] - mu[p]) * rv[p] * gw[c] + bw[c];
    }
}

// ---------------- SE: spatial mean pool per (b,c) ------------------------------
__global__ void k_pool(const float* __restrict__ h1, float* __restrict__ pool)
{
    int bc = blockIdx.x;
    const float* p = h1 + bc * HW;
    float s = 0.f;
    for (int i = threadIdx.x; i < HW; i += 256) s += p[i];
    __shared__ float red[256];
    red[threadIdx.x] = s; __syncthreads();
    for (int o = 128; o > 0; o >>= 1) {
        if (threadIdx.x < o) red[threadIdx.x] += red[threadIdx.x + o];
        __syncthreads();
    }
    if (threadIdx.x == 0) pool[bc] = red[0] * (1.f / 16384.f);
}

// ---------------- SE: FC -> relu -> FC -> sigmoid ------------------------------
__global__ void k_se(const float* __restrict__ pool, const float* __restrict__ w1,
                     const float* __restrict__ w2, float* __restrict__ se)
{
    int t = threadIdx.x;
    if (t >= NB * CB) return;
    int b = t / CB, c = t % CB;
    int gi = c >> 5, j = c & 31;
    const float* pl = pool + b * CB + gi * 32;
    float z0 = 0.f, z1 = 0.f;
    #pragma unroll
    for (int g = 0; g < 32; g++) {
        float pv = pl[g];
        z0 += pv * w1[gi * 64 + g];
        z1 += pv * w1[gi * 64 + 32 + g];
    }
    z0 = fmaxf(z0, 0.f); z1 = fmaxf(z1, 0.f);
    float a = z0 * w2[gi * 64 + j * 2] + z1 * w2[gi * 64 + j * 2 + 1];
    se[t] = 1.f / (1.f + __expf(-a));
}

// ---------------- 6 per-pixel projections (96x96 GEMMs, 12x8 tile) -------------
// 128 threads, smem: Xs only (49152B)
__global__ __launch_bounds__(128, 3)
void k_proj6(const float* __restrict__ l1, const float* __restrict__ h1,
             const float* __restrict__ se,
             const float* __restrict__ Wql, const float* __restrict__ Wkl, const float* __restrict__ Wvl,
             const float* __restrict__ Wqh, const float* __restrict__ Wkh, const float* __restrict__ Wvh,
             float* __restrict__ QL, float* __restrict__ KL, float* __restrict__ VL,
             float* __restrict__ QH, float* __restrict__ KH, float* __restrict__ VH)
{
    extern __shared__ float sm[];
    float* Xs = sm;           // 12288
    int row = blockIdx.x;
    int j = blockIdx.y;
    const float* W; const float* X; float* O; bool useSE;
    switch (j) {
        case 0: W = Wql; X = l1; O = QL; useSE = false; break;
        case 1: W = Wkl; X = l1; O = KL; useSE = false; break;
        case 2: W = Wvl; X = l1; O = VL; useSE = false; break;
        case 3: W = Wqh; X = h1; O = QH; useSE = true;  break;
        case 4: W = Wkh; X = h1; O = KH; useSE = true;  break;
        default: W = Wvh; X = h1; O = VH; useSE = true; break;
    }
    int b = row >> 7, h = row & 127;
    int base = b * CB * HW + h * 128;
    int tid = threadIdx.x;

    for (int i = tid; i < 12288; i += 128) {
        int c = i >> 7, p = i & 127;
        float v = X[base + c * HW + p];
        if (useSE) v *= se[b * CB + c];
        Xs[i] = v;
    }
    __syncthreads();

    int og = tid >> 4, pg = tid & 15;
    ull acc[12][4];
    #pragma unroll
    for (int r = 0; r < 12; r++)
        #pragma unroll
        for (int i = 0; i < 4; i++) acc[r][i] = 0ull;

    gemm12x8g(W, 96, Xs, og, pg, acc);

    #pragma unroll
    for (int r = 0; r < 12; r++) {
        int o = og * 12 + r;
        *(ulonglong2*)&O[base + o * HW + pg * 8]     = make_ulonglong2(acc[r][0], acc[r][1]);
        *(ulonglong2*)&O[base + o * HW + pg * 8 + 4] = make_ulonglong2(acc[r][2], acc[r][3]);
    }
}

// ---------------- zero fold accumulators ---------------------------------------
__global__ void k_zero(float4* __restrict__ a, float4* __restrict__ b)
{
    int n = NELEM / 4;
    for (int i = blockIdx.x * blockDim.x + threadIdx.x; i < n;
         i += gridDim.x * blockDim.x) {
        a[i] = make_float4(0.f, 0.f, 0.f, 0.f);
        b[i] = make_float4(0.f, 0.f, 0.f, 0.f);
    }
}

// ---------------- window cross attention (FFMA2, 2n per thread) ----------------
// grid NWINDOWS, 128 thr, dyn smem 73728B
__global__ __launch_bounds__(128, 3)
void k_attn(const float* __restrict__ QL, const float* __restrict__ KL, const float* __restrict__ VL,
            const float* __restrict__ QH, const float* __restrict__ KH, const float* __restrict__ VH,
            float* __restrict__ accL, float* __restrict__ accH, int shift)
{
    extern __shared__ float sm[];
    float* Qs = sm;            // [96][64]
    float* Kt = sm + 6144;     // [4][64 m][24 d]
    float* Vt = sm + 12288;    // [4][64 m][24 d]

    int win = blockIdx.x;
    int b = win / (NWIN * NWIN);
    int r = win - b * (NWIN * NWIN);
    int wi = r / NWIN, wj = r - wi * NWIN;
    int h0 = wi * 4, w0 = wj * 4;
    int tid = threadIdx.x;

    #pragma unroll 1
    for (int dir = 0; dir < 2; dir++) {
        const float* Qf = dir == 0 ? QL : QH;
        const float* Kf = dir == 0 ? KH : KL;
        const float* Vf = dir == 0 ? VH : VL;
        float* acc = dir == 0 ? accL : accH;

        // gather window (Q kept [c][p], K/V transposed to [head][m][d])
        for (int i = tid; i < 6144; i += 128) {
            int c = i >> 6, p = i & 63;
            int hh = (h0 + (p >> 3) + shift) & 127;
            int ww = (w0 + (p & 7) + shift) & 127;
            int gi = (b * CB + c) * HW + hh * 128 + ww;
            int hd = c / 24, d = c - hd * 24;
            int ti = hd * 1536 + p * 24 + d;
            Qs[i] = Qf[gi];
            Kt[ti] = Kf[gi];
            Vt[ti] = Vf[gi];
        }
        __syncthreads();

        int head = tid >> 5, lane = tid & 31;
        int n0 = lane, n1 = lane + 32;
        const float* Qh = Qs + head * 24 * 64;
        const float* Kb = Kt + head * 1536;
        const float* Vb = Vt + head * 1536;

        ull qp0[12], qp1[12];
        #pragma unroll
        for (int jj = 0; jj < 12; jj++) {
            qp0[jj] = pk2(Qh[(2 * jj) * 64 + n0], Qh[(2 * jj + 1) * 64 + n0]);
            qp1[jj] = pk2(Qh[(2 * jj) * 64 + n1], Qh[(2 * jj + 1) * 64 + n1]);
        }

        ull op0[12], op1[12];
        #pragma unroll
        for (int jj = 0; jj < 12; jj++) { op0[jj] = 0ull; op1[jj] = 0ull; }
        float ssum0 = 0.f, ssum1 = 0.f;

        for (int m = 0; m < 64; m++) {
            const ulonglong2* Kp = (const ulonglong2*)(Kb + m * 24);
            ulonglong2 kk[6];
            #pragma unroll
            for (int jj = 0; jj < 6; jj++) kk[jj] = Kp[jj];
            ull s0 = 0ull, s1 = 0ull;
            #pragma unroll
            for (int jj = 0; jj < 6; jj++) {
                ffma2(s0, qp0[2 * jj],     kk[jj].x);
                ffma2(s0, qp0[2 * jj + 1], kk[jj].y);
                ffma2(s1, qp1[2 * jj],     kk[jj].x);
                ffma2(s1, qp1[2 * jj + 1], kk[jj].y);
            }
            float a0, b0v, a1, b1v;
            upk(s0, a0, b0v); upk(s1, a1, b1v);
            float e0 = __expf((a0 + b0v) * ATT_SCALE);
            float e1 = __expf((a1 + b1v) * ATT_SCALE);
            ssum0 += e0; ssum1 += e1;
            ull ee0 = pk2(e0, e0), ee1 = pk2(e1, e1);
            const ulonglong2* Vp = (const ulonglong2*)(Vb + m * 24);
            #pragma unroll
            for (int jj = 0; jj < 6; jj++) {
                ulonglong2 vv = Vp[jj];
                ffma2(op0[2 * jj],     ee0, vv.x);
                ffma2(op0[2 * jj + 1], ee0, vv.y);
                ffma2(op1[2 * jj],     ee1, vv.x);
                ffma2(op1[2 * jj + 1], ee1, vv.y);
            }
        }
        float inv0 = 1.f / ssum0, inv1 = 1.f / ssum1;

        int cb0 = b * CB + head * 24;
        {
            int ph = n0 >> 3, pw = n0 & 7;
            int base = cb0 * HW + (h0 + ph) * 128 + (w0 + pw);
            #pragma unroll
            for (int jj = 0; jj < 12; jj++) {
                float lo, hi; upk(op0[jj], lo, hi);
                atomicAdd(acc + base + (2 * jj) * HW,     lo * inv0);
                atomicAdd(acc + base + (2 * jj + 1) * HW, hi * inv0);
            }
        }
        {
            int ph = n1 >> 3, pw = n1 & 7;
            int base = cb0 * HW + (h0 + ph) * 128 + (w0 + pw);
            #pragma unroll
            for (int jj = 0; jj < 12; jj++) {
                float lo, hi; upk(op1[jj], lo, hi);
                atomicAdd(acc + base + (2 * jj) * HW,     lo * inv1);
                atomicAdd(acc + base + (2 * jj + 1) * HW, hi * inv1);
            }
        }
        __syncthreads();
    }
}

// ---------------- fold/cnt + output projection + residual (12x8 tile) ----------
// dst = src + lnfield + W_proj * (fold(acc)/cnt)   128 thr, smem 49664B
__global__ __launch_bounds__(128, 3)
void k_foldproj(const float* __restrict__ accL, const float* __restrict__ accH,
                const float* __restrict__ wpl, const float* __restrict__ wph,
                const float* __restrict__ srcL, const float* __restrict__ srcH,
                const float* __restrict__ lnL,  const float* __restrict__ lnH,
                float* __restrict__ dstL, float* __restrict__ dstH, int shift)
{
    extern __shared__ float sm[];
    float* Xs  = sm;            // 12288
    float* rcw = sm + 12288;    // 128

    int t = blockIdx.y;
    const float* A   = t ? accH : accL;
    const float* W   = t ? wph  : wpl;
    const float* src = t ? srcH : srcL;
    const float* lnf = t ? lnH  : lnL;
    float*       dst = t ? dstH : dstL;

    int row = blockIdx.x;
    int b = row >> 7, h = row & 127;
    int hr = (h - shift) & 127;
    float invh = 1.f / cnt1f(hr);
    int tid = threadIdx.x;

    if (tid < 128) {
        int wr = (tid - shift) & 127;
        rcw[tid] = invh * (1.f / cnt1f(wr));
    }
    __syncthreads();

    int abase = b * CB * HW + hr * 128;
    for (int i = tid; i < 12288; i += 128) {
        int c = i >> 7, p = i & 127;
        int wr = (p - shift) & 127;
        Xs[i] = A[abase + c * HW + wr] * rcw[p];
    }
    __syncthreads();

    int og = tid >> 4, pg = tid & 15;
    ull acc[12][4];
    #pragma unroll
    for (int r = 0; r < 12; r++)
        #pragma unroll
        for (int i = 0; i < 4; i++) acc[r][i] = 0ull;

    gemm12x8g(W, 96, Xs, og, pg, acc);

    int base = b * CB * HW + h * 128;
    #pragma unroll
    for (int r = 0; r < 12; r++) {
        int o = og * 12 + r;
        int off0 = base + o * HW + pg * 8;
        ulonglong2 s0 = *(const ulonglong2*)&src[off0];
        ulonglong2 s1 = *(const ulonglong2*)&src[off0 + 4];
        ulonglong2 n0 = *(const ulonglong2*)&lnf[off0];
        ulonglong2 n1 = *(const ulonglong2*)&lnf[off0 + 4];
        ulonglong2 o0 = make_ulonglong2(fadd2(fadd2(s0.x, n0.x), acc[r][0]),
                                        fadd2(fadd2(s0.y, n0.y), acc[r][1]));
        ulonglong2 o1 = make_ulonglong2(fadd2(fadd2(s1.x, n1.x), acc[r][2]),
                                        fadd2(fadd2(s1.y, n1.y), acc[r][3]));
        *(ulonglong2*)&dst[off0]     = o0;
        *(ulonglong2*)&dst[off0 + 4] = o1;
    }
}

// ---------------- MLP (96->384 gelu ->96) + residual (FFMA2) -------------------
// weights from global (L1); smem = Xs + Hs = 98304B -> 2 CTAs/SM
__global__ __launch_bounds__(256, 2)
void k_mlp(const float* __restrict__ xL, const float* __restrict__ xH,
           const float* __restrict__ w1, const float* __restrict__ b1,
           const float* __restrict__ w2, const float* __restrict__ b2,
           float* __restrict__ outL, float* __restrict__ outH)
{
    extern __shared__ float sm[];
    float* Xs = sm;             // 12288
    float* Hs = sm + 12288;     // 12288

    const float* X = blockIdx.y ? xH : xL;
    float*       out = blockIdx.y ? outH : outL;
    int row = blockIdx.x;
    int b = row >> 7, h = row & 127;
    int base = b * CB * HW + h * 128;
    int tid = threadIdx.x;

    for (int i = tid; i < 12288; i += 256) {
        int c = i >> 7, p = i & 127;
        Xs[i] = X[base + c * HW + p];
    }
    __syncthreads();

    int og = tid >> 4, pg = tid & 15;
    ull acc[6][4];
    #pragma unroll
    for (int r = 0; r < 6; r++) {
        float bv = b2[og * 6 + r];
        ull bp = pk2(bv, bv);
        #pragma unroll
        for (int i = 0; i < 4; i++) acc[r][i] = bp;
    }

    #pragma unroll 1
    for (int k = 0; k < 4; k++) {
        ull ha[6][4];
        #pragma unroll
        for (int r = 0; r < 6; r++)
            #pragma unroll
            for (int i = 0; i < 4; i++) ha[r][i] = 0ull;

        gemm6x8g(w1 + k * 96 * 96, 96, Xs, og, pg, ha);

        #pragma unroll
        for (int r = 0; r < 6; r++) {
            float bb = b1[k * 96 + og * 6 + r];
            float v[8];
            upk(ha[r][0], v[0], v[1]); upk(ha[r][1], v[2], v[3]);
            upk(ha[r][2], v[4], v[5]); upk(ha[r][3], v[6], v[7]);
            float g[8];
            #pragma unroll
            for (int i = 0; i < 8; i++) g[i] = gelu_f(v[i] + bb);
            *(float4*)&Hs[(og * 6 + r) * 128 + pg * 8]     = make_float4(g[0], g[1], g[2], g[3]);
            *(float4*)&Hs[(og * 6 + r) * 128 + pg * 8 + 4] = make_float4(g[4], g[5], g[6], g[7]);
        }
        __syncthreads();

        gemm6x8g(w2 + k * 96, 384, Hs, og, pg, acc);
        __syncthreads();
    }

    #pragma unroll
    for (int r = 0; r < 6; r++) {
        int o = og * 6 + r;
        ulonglong2 xa = *(const ulonglong2*)&Xs[o * 128 + pg * 8];
        ulonglong2 xb = *(const ulonglong2*)&Xs[o * 128 + pg * 8 + 4];
        ulonglong2 o0 = make_ulonglong2(fadd2(xa.x, acc[r][0]), fadd2(xa.y, acc[r][1]));
        ulonglong2 o1 = make_ulonglong2(fadd2(xb.x, acc[r][2]), fadd2(xb.y, acc[r][3]));
        *(ulonglong2*)&out[base + o * HW + pg * 8]     = o0;
        *(ulonglong2*)&out[base + o * HW + pg * 8 + 4] = o1;
    }
}

// ---------------- host orchestration -------------------------------------------
static float* symaddr(const void* sym)
{
    void* p = nullptr;
    cudaGetSymbolAddress(&p, sym);
    return (float*)p;
}

extern "C" void kernel_launch(void* const* d_in, const int* in_sizes, int n_in,
                              void* d_out, int out_size)
{
    const float* low    = (const float*)d_in[0];
    const float* high   = (const float*)d_in[1];
    const float* ln1g   = (const float*)d_in[2];
    const float* ln1b   = (const float*)d_in[3];
    const float* ln2g   = (const float*)d_in[4];
    const float* ln2b   = (const float*)d_in[5];
    const float* se_w1  = (const float*)d_in[6];
    const float* se_w2  = (const float*)d_in[7];
    const float* wq_l   = (const float*)d_in[8];
    const float* wk_h   = (const float*)d_in[9];
    const float* wv_h   = (const float*)d_in[10];
    const float* wq_h   = (const float*)d_in[11];
    const float* wk_l   = (const float*)d_in[12];
    const float* wv_l   = (const float*)d_in[13];
    const float* wp_l   = (const float*)d_in[14];
    const float* wp_h   = (const float*)d_in[15];
    const float* mlp_w1 = (const float*)d_in[16];
    const float* mlp_b1 = (const float*)d_in[17];
    const float* mlp_w2 = (const float*)d_in[18];
    const float* mlp_b2 = (const float*)d_in[19];
    float* out = (float*)d_out;

    float* l1   = symaddr(g_l1);    float* h1   = symaddr(g_h1);
    float* QL   = symaddr(g_QL);    float* KL   = symaddr(g_KL);  float* VL = symaddr(g_VL);
    float* QH   = symaddr(g_QH);    float* KH   = symaddr(g_KH);  float* VH = symaddr(g_VH);
    float* accL = symaddr(g_accL);  float* accH = symaddr(g_accH);
    float* low1 = symaddr(g_low1);  float* high1 = symaddr(g_high1);
    float* low2 = symaddr(g_low2);  float* high2 = symaddr(g_high2);
    float* pool = symaddr(g_pool);  float* se    = symaddr(g_se);

    cudaFuncSetAttribute(k_ln,       cudaFuncAttributeMaxDynamicSharedMemorySize, 50176);
    cudaFuncSetAttribute(k_proj6,    cudaFuncAttributeMaxDynamicSharedMemorySize, 49152);
    cudaFuncSetAttribute(k_attn,     cudaFuncAttributeMaxDynamicSharedMemorySize, 73728);
    cudaFuncSetAttribute(k_foldproj, cudaFuncAttributeMaxDynamicSharedMemorySize, 49664);
    cudaFuncSetAttribute(k_mlp,      cudaFuncAttributeMaxDynamicSharedMemorySize, 98304);

    dim3 gRow2(NB * HWIMG, 2);
    dim3 gProj(NB * HWIMG, 6);

    // ---------------- pass 1 (shift = 0, ln1) ----------------
    k_ln<<<gRow2, 256, 50176>>>(low, high, ln1g, ln1b, l1, h1);
    k_pool<<<NB * CB, 256>>>(h1, pool);
    k_se<<<1, 256>>>(pool, se_w1, se_w2, se);
    k_proj6<<<gProj, 128, 49152>>>(l1, h1, se, wq_l, wk_l, wv_l, wq_h, wk_h, wv_h,
                                   QL, KL, VL, QH, KH, VH);
    k_zero<<<1024, 256>>>((float4*)accL, (float4*)accH);
    k_attn<<<NWINDOWS, 128, 73728>>>(QL, KL, VL, QH, KH, VH, accL, accH, 0);
    k_foldproj<<<gRow2, 128, 49664>>>(accL, accH, wp_l, wp_h, low, high, l1, h1,
                                      low1, high1, 0);

    // ---------------- pass 2 (shift = 4, ln2) ----------------
    k_ln<<<gRow2, 256, 50176>>>(low1, high1, ln2g, ln2b, l1, h1);
    k_pool<<<NB * CB, 256>>>(h1, pool);
    k_se<<<1, 256>>>(pool, se_w1, se_w2, se);
    k_proj6<<<gProj, 128, 49152>>>(l1, h1, se, wq_l, wk_l, wv_l, wq_h, wk_h, wv_h,
                                   QL, KL, VL, QH, KH, VH);
    k_zero<<<1024, 256>>>((float4*)accL, (float4*)accH);
    k_attn<<<NWINDOWS, 128, 73728>>>(QL, KL, VL, QH, KH, VH, accL, accH, 4);
    k_foldproj<<<gRow2, 128, 49664>>>(accL, accH, wp_l, wp_h, low1, high1, l1, h1,
                                      low2, high2, 4);

    // ---------------- MLP + residual -> output ----------------
    k_mlp<<<gRow2, 256, 98304>>>(low2, high2, mlp_w1, mlp_b1, mlp_w2, mlp_b2,
                                 out, out + NELEM);
}

// round 16
// speedup vs baseline: 1.5256x; 1.1277x over previous
#include <cuda_runtime.h>
#include <math.h>

#define CB     96
#define HWIMG  128
#define HW     16384          // 128*128
#define NB     2
#define NELEM  3145728        // NB*CB*HW
#define NWIN   31
#define NWINDOWS 1922         // NB*31*31
#define ATT_SCALE 0.20412414523193154f  // 1/sqrt(24)
#define XP     104            // smem pitch (words) for px-major tf32 tiles
#define WP     104            // smem pitch (words) for weight tiles

typedef unsigned long long ull;

// ---------------- packed f32x2 helpers (attention kernel) ----------------------
__device__ __forceinline__ ull pk2(float lo, float hi) {
    ull r; asm("mov.b64 %0,{%1,%2};" : "=l"(r) : "f"(lo), "f"(hi)); return r;
}
__device__ __forceinline__ void upk(ull v, float& lo, float& hi) {
    asm("mov.b64 {%0,%1},%2;" : "=f"(lo), "=f"(hi) : "l"(v));
}
__device__ __forceinline__ void ffma2(ull& d, ull a, ull b) {
    asm("fma.rn.f32x2 %0,%1,%2,%0;" : "+l"(d) : "l"(a), "l"(b));
}

// ---------------- tf32 mma helpers ---------------------------------------------
__device__ __forceinline__ unsigned f2tf(float f) {
    unsigned u; asm("cvt.rna.tf32.f32 %0, %1;" : "=r"(u) : "f"(f)); return u;
}
__device__ __forceinline__ void mma_tf32(float d[4], const unsigned a[4], const unsigned b[2]) {
    asm volatile("mma.sync.aligned.m16n8k8.row.col.f32.tf32.tf32.f32 "
        "{%0,%1,%2,%3}, {%4,%5,%6,%7}, {%8,%9}, {%0,%1,%2,%3};"
        : "+f"(d[0]), "+f"(d[1]), "+f"(d[2]), "+f"(d[3])
        : "r"(a[0]), "r"(a[1]), "r"(a[2]), "r"(a[3]), "r"(b[0]), "r"(b[1]));
}

// Warp-level GEMM: D[16px x 96out] += Xt[16px x 96k] * Ws[96out x 96k]^T
// Xt px-major pitch XP (tf32 words), Ws out-major pitch WP (tf32 words).
// Fragment banks: 8*gr + tig -> conflict-free for both A and B (pitch%32==8).
__device__ __forceinline__ void wgemm16x96(const unsigned* __restrict__ Xt,
                                           const unsigned* __restrict__ Ws,
                                           int px0, int gr, int tig, float acc[12][4])
{
    #pragma unroll 1
    for (int k0 = 0; k0 < 96; k0 += 8) {
        unsigned a[4];
        a[0] = Xt[(px0 + gr) * XP + k0 + tig];
        a[1] = Xt[(px0 + gr + 8) * XP + k0 + tig];
        a[2] = Xt[(px0 + gr) * XP + k0 + tig + 4];
        a[3] = Xt[(px0 + gr + 8) * XP + k0 + tig + 4];
        #pragma unroll
        for (int n = 0; n < 12; n++) {
            unsigned b[2];
            b[0] = Ws[(n * 8 + gr) * WP + k0 + tig];
            b[1] = Ws[(n * 8 + gr) * WP + k0 + tig + 4];
            mma_tf32(acc[n], a, b);
        }
    }
}

// ---------------- scratch (static device globals; alloc-free rule) -------------
__device__ float g_l1[NELEM], g_h1[NELEM];
__device__ float g_QL[NELEM], g_KL[NELEM], g_VL[NELEM];
__device__ float g_QH[NELEM], g_KH[NELEM], g_VH[NELEM];
__device__ float g_accL[NELEM], g_accH[NELEM];
__device__ float g_low1[NELEM], g_high1[NELEM];
__device__ float g_low2[NELEM], g_high2[NELEM];
__device__ float g_pool[NB*CB], g_se[NB*CB];

// ---------------- helpers ------------------------------------------------------
__device__ __forceinline__ float cnt1f(int h) {
    int imin = (h <= 7) ? 0 : ((h - 4) >> 2);
    int imax = min(30, h >> 2);
    return (float)(imax - imin + 1);
}

__device__ __forceinline__ float gelu_f(float v) {
    float u = 0.7978845608028654f * (v + 0.044715f * v * v * v);
    float t = 1.f - 2.f / (__expf(2.f * u) + 1.f);
    return 0.5f * v * (1.f + t);
}

// ---------------- LN over channel axis, per pixel ------------------------------
__global__ void k_ln(const float* __restrict__ srcL, const float* __restrict__ srcH,
                     const float* __restrict__ gw,  const float* __restrict__ bw,
                     float* __restrict__ dstL, float* __restrict__ dstH)
{
    extern __shared__ float smf[];
    float* Xs = smf;             // 96*128
    float* mu = smf + 12288;
    float* rv = smf + 12416;
    const float* src = blockIdx.y ? srcH : srcL;
    float*       dst = blockIdx.y ? dstH : dstL;
    int row = blockIdx.x;
    int b = row >> 7, h = row & 127;
    int base = b * CB * HW + h * 128;
    int tid = threadIdx.x;

    for (int i = tid; i < 12288; i += 256) {
        int c = i >> 7, p = i & 127;
        Xs[i] = src[base + c * HW + p];
    }
    __syncthreads();
    if (tid < 128) {
        float s = 0.f, s2 = 0.f;
        #pragma unroll 8
        for (int c = 0; c < CB; c++) {
            float v = Xs[c * 128 + tid];
            s += v; s2 += v * v;
        }
        float m = s * (1.f / 96.f);
        float var = s2 * (1.f / 96.f) - m * m;
        mu[tid] = m;
        rv[tid] = rsqrtf(var + 1e-5f);
    }
    __syncthreads();
    for (int i = tid; i < 12288; i += 256) {
        int c = i >> 7, p = i & 127;
        dst[base + c * HW + p] = (Xs[i] - mu[p]) * rv[p] * gw[c] + bw[c];
    }
}

// ---------------- SE: spatial mean pool per (b,c) ------------------------------
__global__ void k_pool(const float* __restrict__ h1, float* __restrict__ pool)
{
    int bc = blockIdx.x;
    const float* p = h1 + bc * HW;
    float s = 0.f;
    for (int i = threadIdx.x; i < HW; i += 256) s += p[i];
    __shared__ float red[256];
    red[threadIdx.x] = s; __syncthreads();
    for (int o = 128; o > 0; o >>= 1) {
        if (threadIdx.x < o) red[threadIdx.x] += red[threadIdx.x + o];
        __syncthreads();
    }
    if (threadIdx.x == 0) pool[bc] = red[0] * (1.f / 16384.f);
}

// ---------------- SE: FC -> relu -> FC -> sigmoid ------------------------------
__global__ void k_se(const float* __restrict__ pool, const float* __restrict__ w1,
                     const float* __restrict__ w2, float* __restrict__ se)
{
    int t = threadIdx.x;
    if (t >= NB * CB) return;
    int b = t / CB, c = t % CB;
    int gi = c >> 5, j = c & 31;
    const float* pl = pool + b * CB + gi * 32;
    float z0 = 0.f, z1 = 0.f;
    #pragma unroll
    for (int g = 0; g < 32; g++) {
        float pv = pl[g];
        z0 += pv * w1[gi * 64 + g];
        z1 += pv * w1[gi * 64 + 32 + g];
    }
    z0 = fmaxf(z0, 0.f); z1 = fmaxf(z1, 0.f);
    float a = z0 * w2[gi * 64 + j * 2] + z1 * w2[gi * 64 + j * 2 + 1];
    se[t] = 1.f / (1.f + __expf(-a));
}

// ---------------- 6 per-pixel projections (tf32 mma) ---------------------------
// 256 thr (8 warps), smem: Xt[128][XP] + Ws[96][WP] tf32 words = 93184 B
__global__ __launch_bounds__(256, 2)
void k_proj6(const float* __restrict__ l1, const float* __restrict__ h1,
             const float* __restrict__ se,
             const float* __restrict__ Wql, const float* __restrict__ Wkl, const float* __restrict__ Wvl,
             const float* __restrict__ Wqh, const float* __restrict__ Wkh, const float* __restrict__ Wvh,
             float* __restrict__ QL, float* __restrict__ KL, float* __restrict__ VL,
             float* __restrict__ QH, float* __restrict__ KH, float* __restrict__ VH)
{
    extern __shared__ unsigned smu[];
    unsigned* Xt = smu;               // 128*XP
    unsigned* Ws = smu + 128 * XP;    // 96*WP

    int row = blockIdx.x;
    int j = blockIdx.y;
    const float* W; const float* X; float* O; bool useSE;
    switch (j) {
        case 0: W = Wql; X = l1; O = QL; useSE = false; break;
        case 1: W = Wkl; X = l1; O = KL; useSE = false; break;
        case 2: W = Wvl; X = l1; O = VL; useSE = false; break;
        case 3: W = Wqh; X = h1; O = QH; useSE = true;  break;
        case 4: W = Wkh; X = h1; O = KH; useSE = true;  break;
        default: W = Wvh; X = h1; O = VH; useSE = true; break;
    }
    int b = row >> 7, h = row & 127;
    int base = b * CB * HW + h * 128;
    int tid = threadIdx.x;

    for (int i = tid; i < 12288; i += 256) {
        int c = i >> 7, p = i & 127;
        float v = X[base + c * HW + p];
        if (useSE) v *= se[b * CB + c];
        Xt[p * XP + c] = f2tf(v);
    }
    for (int i = tid; i < 9216; i += 256) {
        int o = i / 96, c = i - o * 96;
        Ws[o * WP + c] = f2tf(W[i]);
    }
    __syncthreads();

    int warp = tid >> 5, lane = tid & 31;
    int gr = lane >> 2, tig = lane & 3;
    int px0 = warp * 16;

    float acc[12][4];
    #pragma unroll
    for (int n = 0; n < 12; n++)
        #pragma unroll
        for (int i = 0; i < 4; i++) acc[n][i] = 0.f;

    wgemm16x96(Xt, Ws, px0, gr, tig, acc);

    #pragma unroll
    for (int n = 0; n < 12; n++) {
        int o = n * 8 + 2 * tig;
        O[base + o * HW + px0 + gr]           = acc[n][0];
        O[base + (o + 1) * HW + px0 + gr]     = acc[n][1];
        O[base + o * HW + px0 + gr + 8]       = acc[n][2];
        O[base + (o + 1) * HW + px0 + gr + 8] = acc[n][3];
    }
}

// ---------------- zero fold accumulators ---------------------------------------
__global__ void k_zero(float4* __restrict__ a, float4* __restrict__ b)
{
    int n = NELEM / 4;
    for (int i = blockIdx.x * blockDim.x + threadIdx.x; i < n;
         i += gridDim.x * blockDim.x) {
        a[i] = make_float4(0.f, 0.f, 0.f, 0.f);
        b[i] = make_float4(0.f, 0.f, 0.f, 0.f);
    }
}

// ---------------- window cross attention (FFMA2, 2n per thread) ----------------
// grid NWINDOWS, 128 thr, dyn smem 73728B
__global__ __launch_bounds__(128, 3)
void k_attn(const float* __restrict__ QL, const float* __restrict__ KL, const float* __restrict__ VL,
            const float* __restrict__ QH, const float* __restrict__ KH, const float* __restrict__ VH,
            float* __restrict__ accL, float* __restrict__ accH, int shift)
{
    extern __shared__ float sma[];
    float* Qs = sma;            // [96][64]
    float* Kt = sma + 6144;     // [4][64 m][24 d]
    float* Vt = sma + 12288;    // [4][64 m][24 d]

    int win = blockIdx.x;
    int b = win / (NWIN * NWIN);
    int r = win - b * (NWIN * NWIN);
    int wi = r / NWIN, wj = r - wi * NWIN;
    int h0 = wi * 4, w0 = wj * 4;
    int tid = threadIdx.x;

    #pragma unroll 1
    for (int dir = 0; dir < 2; dir++) {
        const float* Qf = dir == 0 ? QL : QH;
        const float* Kf = dir == 0 ? KH : KL;
        const float* Vf = dir == 0 ? VH : VL;
        float* acc = dir == 0 ? accL : accH;

        for (int i = tid; i < 6144; i += 128) {
            int c = i >> 6, p = i & 63;
            int hh = (h0 + (p >> 3) + shift) & 127;
            int ww = (w0 + (p & 7) + shift) & 127;
            int gi = (b * CB + c) * HW + hh * 128 + ww;
            int hd = c / 24, d = c - hd * 24;
            int ti = hd * 1536 + p * 24 + d;
            Qs[i] = Qf[gi];
            Kt[ti] = Kf[gi];
            Vt[ti] = Vf[gi];
        }
        __syncthreads();

        int head = tid >> 5, lane = tid & 31;
        int n0 = lane, n1 = lane + 32;
        const float* Qh = Qs + head * 24 * 64;
        const float* Kb = Kt + head * 1536;
        const float* Vb = Vt + head * 1536;

        ull qp0[12], qp1[12];
        #pragma unroll
        for (int jj = 0; jj < 12; jj++) {
            qp0[jj] = pk2(Qh[(2 * jj) * 64 + n0], Qh[(2 * jj + 1) * 64 + n0]);
            qp1[jj] = pk2(Qh[(2 * jj) * 64 + n1], Qh[(2 * jj + 1) * 64 + n1]);
        }

        ull op0[12], op1[12];
        #pragma unroll
        for (int jj = 0; jj < 12; jj++) { op0[jj] = 0ull; op1[jj] = 0ull; }
        float ssum0 = 0.f, ssum1 = 0.f;

        for (int m = 0; m < 64; m++) {
            const ulonglong2* Kp = (const ulonglong2*)(Kb + m * 24);
            ulonglong2 kk[6];
            #pragma unroll
            for (int jj = 0; jj < 6; jj++) kk[jj] = Kp[jj];
            ull s0 = 0ull, s1 = 0ull;
            #pragma unroll
            for (int jj = 0; jj < 6; jj++) {
                ffma2(s0, qp0[2 * jj],     kk[jj].x);
                ffma2(s0, qp0[2 * jj + 1], kk[jj].y);
                ffma2(s1, qp1[2 * jj],     kk[jj].x);
                ffma2(s1, qp1[2 * jj + 1], kk[jj].y);
            }
            float a0, b0v, a1, b1v;
            upk(s0, a0, b0v); upk(s1, a1, b1v);
            float e0 = __expf((a0 + b0v) * ATT_SCALE);
            float e1 = __expf((a1 + b1v) * ATT_SCALE);
            ssum0 += e0; ssum1 += e1;
            ull ee0 = pk2(e0, e0), ee1 = pk2(e1, e1);
            const ulonglong2* Vp = (const ulonglong2*)(Vb + m * 24);
            #pragma unroll
            for (int jj = 0; jj < 6; jj++) {
                ulonglong2 vv = Vp[jj];
                ffma2(op0[2 * jj],     ee0, vv.x);
                ffma2(op0[2 * jj + 1], ee0, vv.y);
                ffma2(op1[2 * jj],     ee1, vv.x);
                ffma2(op1[2 * jj + 1], ee1, vv.y);
            }
        }
        float inv0 = 1.f / ssum0, inv1 = 1.f / ssum1;

        int cb0 = b * CB + head * 24;
        {
            int ph = n0 >> 3, pw = n0 & 7;
            int base = cb0 * HW + (h0 + ph) * 128 + (w0 + pw);
            #pragma unroll
            for (int jj = 0; jj < 12; jj++) {
                float lo, hi; upk(op0[jj], lo, hi);
                atomicAdd(acc + base + (2 * jj) * HW,     lo * inv0);
                atomicAdd(acc + base + (2 * jj + 1) * HW, hi * inv0);
            }
        }
        {
            int ph = n1 >> 3, pw = n1 & 7;
            int base = cb0 * HW + (h0 + ph) * 128 + (w0 + pw);
            #pragma unroll
            for (int jj = 0; jj < 12; jj++) {
                float lo, hi; upk(op1[jj], lo, hi);
                atomicAdd(acc + base + (2 * jj) * HW,     lo * inv1);
                atomicAdd(acc + base + (2 * jj + 1) * HW, hi * inv1);
            }
        }
        __syncthreads();
    }
}

// ---------------- fold/cnt + output projection + residual (tf32 mma) -----------
// dst = src + lnfield + W_proj * (fold(acc)/cnt)
// 256 thr, smem: Xt + Ws + rcw = 93696 B
__global__ __launch_bounds__(256, 2)
void k_foldproj(const float* __restrict__ accL, const float* __restrict__ accH,
                const float* __restrict__ wpl, const float* __restrict__ wph,
                const float* __restrict__ srcL, const float* __restrict__ srcH,
                const float* __restrict__ lnL,  const float* __restrict__ lnH,
                float* __restrict__ dstL, float* __restrict__ dstH, int shift)
{
    extern __shared__ unsigned smu2[];
    unsigned* Xt = smu2;                 // 128*XP
    unsigned* Ws = smu2 + 128 * XP;      // 96*WP
    float*    rcw = (float*)(smu2 + 128 * XP + 96 * WP);  // 128

    int t = blockIdx.y;
    const float* A   = t ? accH : accL;
    const float* W   = t ? wph  : wpl;
    const float* src = t ? srcH : srcL;
    const float* lnf = t ? lnH  : lnL;
    float*       dst = t ? dstH : dstL;

    int row = blockIdx.x;
    int b = row >> 7, h = row & 127;
    int hr = (h - shift) & 127;
    float invh = 1.f / cnt1f(hr);
    int tid = threadIdx.x;

    if (tid < 128) {
        int wr = (tid - shift) & 127;
        rcw[tid] = invh * (1.f / cnt1f(wr));
    }
    __syncthreads();

    int abase = b * CB * HW + hr * 128;
    for (int i = tid; i < 12288; i += 256) {
        int c = i >> 7, p = i & 127;
        int wr = (p - shift) & 127;
        Xt[p * XP + c] = f2tf(A[abase + c * HW + wr] * rcw[p]);
    }
    for (int i = tid; i < 9216; i += 256) {
        int o = i / 96, c = i - o * 96;
        Ws[o * WP + c] = f2tf(W[i]);
    }
    __syncthreads();

    int warp = tid >> 5, lane = tid & 31;
    int gr = lane >> 2, tig = lane & 3;
    int px0 = warp * 16;

    float acc[12][4];
    #pragma unroll
    for (int n = 0; n < 12; n++)
        #pragma unroll
        for (int i = 0; i < 4; i++) acc[n][i] = 0.f;

    wgemm16x96(Xt, Ws, px0, gr, tig, acc);

    int base = b * CB * HW + h * 128;
    #pragma unroll
    for (int n = 0; n < 12; n++) {
        int o = n * 8 + 2 * tig;
        int i00 = base + o * HW + px0 + gr;
        int i10 = base + (o + 1) * HW + px0 + gr;
        dst[i00]     = src[i00]     + lnf[i00]     + acc[n][0];
        dst[i10]     = src[i10]     + lnf[i10]     + acc[n][1];
        dst[i00 + 8] = src[i00 + 8] + lnf[i00 + 8] + acc[n][2];
        dst[i10 + 8] = src[i10 + 8] + lnf[i10 + 8] + acc[n][3];
    }
}

// ---------------- MLP (96->384 gelu ->96) + residual (tf32 mma) ----------------
// 256 thr, smem: Xt + Ht + Wb = (128*XP + 128*XP + 96*WP)*4 = 146432 B, 1 CTA/SM
__global__ __launch_bounds__(256, 1)
void k_mlp(const float* __restrict__ xL, const float* __restrict__ xH,
           const float* __restrict__ w1, const float* __restrict__ b1,
           const float* __restrict__ w2, const float* __restrict__ b2,
           float* __restrict__ outL, float* __restrict__ outH)
{
    extern __shared__ unsigned smu3[];
    unsigned* Xt = smu3;                   // 128*XP
    unsigned* Ht = smu3 + 128 * XP;        // 128*XP
    unsigned* Wb = smu3 + 256 * XP;        // 96*WP

    const float* X = blockIdx.y ? xH : xL;
    float*       out = blockIdx.y ? outH : outL;
    int row = blockIdx.x;
    int b = row >> 7, h = row & 127;
    int base = b * CB * HW + h * 128;
    int tid = threadIdx.x;

    for (int i = tid; i < 12288; i += 256) {
        int c = i >> 7, p = i & 127;
        Xt[p * XP + c] = f2tf(X[base + c * HW + p]);
    }

    int warp = tid >> 5, lane = tid & 31;
    int gr = lane >> 2, tig = lane & 3;
    int px0 = warp * 16;

    float acc2[12][4];
    #pragma unroll
    for (int n = 0; n < 12; n++) {
        int o = n * 8 + 2 * tig;
        float bo0 = b2[o], bo1 = b2[o + 1];
        acc2[n][0] = bo0; acc2[n][1] = bo1;
        acc2[n][2] = bo0; acc2[n][3] = bo1;
    }
    __syncthreads();

    #pragma unroll 1
    for (int k = 0; k < 4; k++) {
        // stage w1 chunk [96h][96c]
        for (int i = tid; i < 9216; i += 256) {
            int o = i / 96, c = i - o * 96;
            Wb[o * WP + c] = f2tf(w1[k * 9216 + i]);
        }
        __syncthreads();

        float acc1[12][4];
        #pragma unroll
        for (int n = 0; n < 12; n++)
            #pragma unroll
            for (int i = 0; i < 4; i++) acc1[n][i] = 0.f;

        wgemm16x96(Xt, Wb, px0, gr, tig, acc1);
        __syncthreads();   // all warps done with Wb before overwrite

        // gelu + write Ht (tf32), then stage w2 chunk
        #pragma unroll
        for (int n = 0; n < 12; n++) {
            int hl = n * 8 + 2 * tig;
            int gh = k * 96 + hl;
            float bb0 = b1[gh], bb1 = b1[gh + 1];
            Ht[(px0 + gr) * XP + hl]         = f2tf(gelu_f(acc1[n][0] + bb0));
            Ht[(px0 + gr) * XP + hl + 1]     = f2tf(gelu_f(acc1[n][1] + bb1));
            Ht[(px0 + gr + 8) * XP + hl]     = f2tf(gelu_f(acc1[n][2] + bb0));
            Ht[(px0 + gr + 8) * XP + hl + 1] = f2tf(gelu_f(acc1[n][3] + bb1));
        }
        for (int i = tid; i < 9216; i += 256) {
            int o = i / 96, c = i - o * 96;
            Wb[o * WP + c] = f2tf(w2[o * 384 + k * 96 + c]);
        }
        __syncthreads();

        wgemm16x96(Ht, Wb, px0, gr, tig, acc2);
        __syncthreads();   // before next chunk's staging / Ht overwrite
    }

    // residual with exact fp32 input reloaded from global
    #pragma unroll
    for (int n = 0; n < 12; n++) {
        int o = n * 8 + 2 * tig;
        int i00 = base + o * HW + px0 + gr;
        int i10 = base + (o + 1) * HW + px0 + gr;
        out[i00]     = X[i00]     + acc2[n][0];
        out[i10]     = X[i10]     + acc2[n][1];
        out[i00 + 8] = X[i00 + 8] + acc2[n][2];
        out[i10 + 8] = X[i10 + 8] + acc2[n][3];
    }
}

// ---------------- host orchestration -------------------------------------------
static float* symaddr(const void* sym)
{
    void* p = nullptr;
    cudaGetSymbolAddress(&p, sym);
    return (float*)p;
}

extern "C" void kernel_launch(void* const* d_in, const int* in_sizes, int n_in,
                              void* d_out, int out_size)
{
    const float* low    = (const float*)d_in[0];
    const float* high   = (const float*)d_in[1];
    const float* ln1g   = (const float*)d_in[2];
    const float* ln1b   = (const float*)d_in[3];
    const float* ln2g   = (const float*)d_in[4];
    const float* ln2b   = (const float*)d_in[5];
    const float* se_w1  = (const float*)d_in[6];
    const float* se_w2  = (const float*)d_in[7];
    const float* wq_l   = (const float*)d_in[8];
    const float* wk_h   = (const float*)d_in[9];
    const float* wv_h   = (const float*)d_in[10];
    const float* wq_h   = (const float*)d_in[11];
    const float* wk_l   = (const float*)d_in[12];
    const float* wv_l   = (const float*)d_in[13];
    const float* wp_l   = (const float*)d_in[14];
    const float* wp_h   = (const float*)d_in[15];
    const float* mlp_w1 = (const float*)d_in[16];
    const float* mlp_b1 = (const float*)d_in[17];
    const float* mlp_w2 = (const float*)d_in[18];
    const float* mlp_b2 = (const float*)d_in[19];
    float* out = (float*)d_out;

    float* l1   = symaddr(g_l1);    float* h1   = symaddr(g_h1);
    float* QL   = symaddr(g_QL);    float* KL   = symaddr(g_KL);  float* VL = symaddr(g_VL);
    float* QH   = symaddr(g_QH);    float* KH   = symaddr(g_KH);  float* VH = symaddr(g_VH);
    float* accL = symaddr(g_accL);  float* accH = symaddr(g_accH);
    float* low1 = symaddr(g_low1);  float* high1 = symaddr(g_high1);
    float* low2 = symaddr(g_low2);  float* high2 = symaddr(g_high2);
    float* pool = symaddr(g_pool);  float* se    = symaddr(g_se);

    const int PROJ_SMEM = (128 * XP + 96 * WP) * 4;           // 93184
    const int FOLD_SMEM = (128 * XP + 96 * WP) * 4 + 512;     // 93696
    const int MLP_SMEM  = (256 * XP + 96 * WP) * 4;           // 146432

    cudaFuncSetAttribute(k_ln,       cudaFuncAttributeMaxDynamicSharedMemorySize, 50176);
    cudaFuncSetAttribute(k_proj6,    cudaFuncAttributeMaxDynamicSharedMemorySize, PROJ_SMEM);
    cudaFuncSetAttribute(k_attn,     cudaFuncAttributeMaxDynamicSharedMemorySize, 73728);
    cudaFuncSetAttribute(k_foldproj, cudaFuncAttributeMaxDynamicSharedMemorySize, FOLD_SMEM);
    cudaFuncSetAttribute(k_mlp,      cudaFuncAttributeMaxDynamicSharedMemorySize, MLP_SMEM);

    dim3 gRow2(NB * HWIMG, 2);
    dim3 gProj(NB * HWIMG, 6);

    // ---------------- pass 1 (shift = 0, ln1) ----------------
    k_ln<<<gRow2, 256, 50176>>>(low, high, ln1g, ln1b, l1, h1);
    k_pool<<<NB * CB, 256>>>(h1, pool);
    k_se<<<1, 256>>>(pool, se_w1, se_w2, se);
    k_proj6<<<gProj, 256, PROJ_SMEM>>>(l1, h1, se, wq_l, wk_l, wv_l, wq_h, wk_h, wv_h,
                                       QL, KL, VL, QH, KH, VH);
    k_zero<<<1024, 256>>>((float4*)accL, (float4*)accH);
    k_attn<<<NWINDOWS, 128, 73728>>>(QL, KL, VL, QH, KH, VH, accL, accH, 0);
    k_foldproj<<<gRow2, 256, FOLD_SMEM>>>(accL, accH, wp_l, wp_h, low, high, l1, h1,
                                          low1, high1, 0);

    // ---------------- pass 2 (shift = 4, ln2) ----------------
    k_ln<<<gRow2, 256, 50176>>>(low1, high1, ln2g, ln2b, l1, h1);
    k_pool<<<NB * CB, 256>>>(h1, pool);
    k_se<<<1, 256>>>(pool, se_w1, se_w2, se);
    k_proj6<<<gProj, 256, PROJ_SMEM>>>(l1, h1, se, wq_l, wk_l, wv_l, wq_h, wk_h, wv_h,
                                       QL, KL, VL, QH, KH, VH);
    k_zero<<<1024, 256>>>((float4*)accL, (float4*)accH);
    k_attn<<<NWINDOWS, 128, 73728>>>(QL, KL, VL, QH, KH, VH, accL, accH, 4);
    k_foldproj<<<gRow2, 256, FOLD_SMEM>>>(accL, accH, wp_l, wp_h, low1, high1, l1, h1,
                                          low2, high2, 4);

    // ---------------- MLP + residual -> output ----------------
    k_mlp<<<gRow2, 256, MLP_SMEM>>>(low2, high2, mlp_w1, mlp_b1, mlp_w2, mlp_b2,
                                    out, out + NELEM);
}